// round 1
// baseline (speedup 1.0000x reference)
#include <cuda_runtime.h>
#include <math.h>

#define B_   1024
#define S_   50
#define E_   300
#define H_   200
#define G3_  600      // 3H
#define M_   (B_*S_)  // 51200

// ---------------- scratch (device globals; no allocations) ----------------
__device__ float g_gxf[(size_t)M_ * G3_];     // 122.9 MB
__device__ float g_gxb[(size_t)M_ * G3_];     // 122.9 MB
__device__ float g_hidden[(size_t)M_ * 2 * H_]; // 81.9 MB
__device__ float g_sent[(size_t)M_ * H_];     // 41 MB
__device__ float g_baseb[M_];
__device__ float g_avg[B_ * H_];
__device__ float g_tmp[B_ * H_];
__device__ float g_doc[B_ * H_];
__device__ float g_WhhTf[H_ * G3_];
__device__ float g_WhhTb[H_ * G3_];
__device__ float g_WnovT[H_ * H_];

// ---------------- small utility kernels ----------------
__global__ void transpose_k(float* __restrict__ dst, const float* __restrict__ src,
                            int rows, int cols) {
    int i = blockIdx.x * blockDim.x + threadIdx.x;
    if (i < rows * cols) {
        int r = i / cols, c = i % cols;
        dst[c * rows + r] = src[i];
    }
}

// ---------------- generic SGEMM: C[m,n] = act(sum_k A[m,k]*B[n,k] + bias[n]) ----
// A: [M,K] row-major; Bm: [N,K] row-major (i.e. C = A * Bm^T). M % 128 == 0 assumed.
template <int ACT>
__global__ void sgemm_nt(const float* __restrict__ A, const float* __restrict__ Bm,
                         const float* __restrict__ bias, float* __restrict__ C,
                         int M, int N, int K) {
    __shared__ float As[8][128];
    __shared__ float Bs[8][128];
    int tid = threadIdx.x;
    int tx = tid & 15, ty = tid >> 4;
    int m0 = blockIdx.y * 128, n0 = blockIdx.x * 128;
    float acc[8][8];
#pragma unroll
    for (int i = 0; i < 8; i++)
#pragma unroll
        for (int j = 0; j < 8; j++) acc[i][j] = 0.f;

    int lr = tid >> 1;     // 0..127 : row within tile
    int lq = tid & 1;      // 0..1   : which 4-wide k chunk

    for (int k0 = 0; k0 < K; k0 += 8) {
        int m = m0 + lr;
        int n = n0 + lr;
        bool nok = (n < N);
#pragma unroll
        for (int i = 0; i < 4; i++) {
            int k = k0 + lq * 4 + i;
            As[lq * 4 + i][lr] = (k < K) ? A[(size_t)m * K + k] : 0.f;
            Bs[lq * 4 + i][lr] = (nok && k < K) ? Bm[(size_t)n * K + k] : 0.f;
        }
        __syncthreads();
#pragma unroll
        for (int kk = 0; kk < 8; kk++) {
            float a[8], b[8];
            float4 a0 = *(const float4*)&As[kk][ty * 8];
            float4 a1 = *(const float4*)&As[kk][ty * 8 + 4];
            float4 b0 = *(const float4*)&Bs[kk][tx * 8];
            float4 b1 = *(const float4*)&Bs[kk][tx * 8 + 4];
            a[0]=a0.x; a[1]=a0.y; a[2]=a0.z; a[3]=a0.w;
            a[4]=a1.x; a[5]=a1.y; a[6]=a1.z; a[7]=a1.w;
            b[0]=b0.x; b[1]=b0.y; b[2]=b0.z; b[3]=b0.w;
            b[4]=b1.x; b[5]=b1.y; b[6]=b1.z; b[7]=b1.w;
#pragma unroll
            for (int i = 0; i < 8; i++)
#pragma unroll
                for (int j = 0; j < 8; j++) acc[i][j] += a[i] * b[j];
        }
        __syncthreads();
    }

#pragma unroll
    for (int i = 0; i < 8; i++) {
        int m = m0 + ty * 8 + i;
#pragma unroll
        for (int j = 0; j < 8; j++) {
            int n = n0 + tx * 8 + j;
            if (n < N) {
                float v = acc[i][j] + (bias ? bias[n] : 0.f);
                if (ACT == 1) v = fmaxf(v, 0.f);
                if (ACT == 2) v = tanhf(v);
                C[(size_t)m * N + n] = v;
            }
        }
    }
}

// ---------------- bidirectional GRU recurrence (persistent per-block) ----------
// grid (64, 2): blockIdx.y = direction; 16 batch rows per block; 608 threads.
// dyn smem: hs[16][200] + ghs[16][600]  = 51200 B
__global__ void gru_kernel(const float* __restrict__ gxf, const float* __restrict__ gxb,
                           const float* __restrict__ WhhTf, const float* __restrict__ WhhTb,
                           const float* __restrict__ bhhf, const float* __restrict__ bhhb,
                           float* __restrict__ hidden) {
    extern __shared__ float sm[];
    float* hs  = sm;             // [16][200]
    float* ghs = sm + 16 * 200;  // [16][600]
    int dir = blockIdx.y;
    const float* gx   = dir ? gxb   : gxf;
    const float* WhhT = dir ? WhhTb : WhhTf;
    const float* bhh  = dir ? bhhb  : bhhf;
    int b0 = blockIdx.x * 16;
    int tid = threadIdx.x;

    for (int i = tid; i < 16 * 200; i += blockDim.x) hs[i] = 0.f;
    __syncthreads();

    for (int t = 0; t < S_; t++) {
        int s = dir ? (S_ - 1 - t) : t;
        if (tid < 600) {
            float acc[16];
            float bb = bhh[tid];
#pragma unroll
            for (int r = 0; r < 16; r++) acc[r] = bb;
            for (int k = 0; k < 200; k += 4) {
                float w0 = WhhT[(k + 0) * 600 + tid];
                float w1 = WhhT[(k + 1) * 600 + tid];
                float w2 = WhhT[(k + 2) * 600 + tid];
                float w3 = WhhT[(k + 3) * 600 + tid];
#pragma unroll
                for (int r = 0; r < 16; r++) {
                    float4 h4 = *(const float4*)&hs[r * 200 + k];
                    acc[r] += w0 * h4.x + w1 * h4.y + w2 * h4.z + w3 * h4.w;
                }
            }
#pragma unroll
            for (int r = 0; r < 16; r++) ghs[r * 600 + tid] = acc[r];
        }
        __syncthreads();
        for (int idx = tid; idx < 16 * 200; idx += blockDim.x) {
            int r = idx / 200, j = idx % 200;
            const float* gxr = gx + ((size_t)((b0 + r) * S_ + s)) * 600;
            float gr = ghs[r * 600 + j];
            float gz = ghs[r * 600 + 200 + j];
            float gn = ghs[r * 600 + 400 + j];
            float rg = 1.f / (1.f + __expf(-(gxr[j] + gr)));
            float zg = 1.f / (1.f + __expf(-(gxr[200 + j] + gz)));
            float nn = tanhf(gxr[400 + j] + rg * gn);
            float hprev = hs[r * 200 + j];
            float hnew = (1.f - zg) * nn + zg * hprev;
            hs[r * 200 + j] = hnew;
            hidden[((size_t)((b0 + r) * S_ + s)) * 400 + dir * 200 + j] = hnew;
        }
        __syncthreads();
    }
}

// ---------------- avg over sequence ----------------
__global__ void avg_kernel(const float* __restrict__ sent, const int* __restrict__ length,
                           float* __restrict__ avg) {
    int i = blockIdx.x * blockDim.x + threadIdx.x;
    if (i < B_ * H_) {
        int b = i / H_, h = i % H_;
        float s = 0.f;
        for (int t = 0; t < S_; t++) s += sent[((size_t)(b * S_ + t)) * H_ + h];
        avg[i] = s / (float)length[b];
    }
}

// ---------------- base = content + salience + pos logits + scalars -------------
__global__ void base_kernel(const float* __restrict__ sent, const float* __restrict__ wcont,
                            const float* __restrict__ doc,
                            const int* __restrict__ apos, const int* __restrict__ rpos,
                            const float* __restrict__ apos_table, const float* __restrict__ rpos_table,
                            const float* __restrict__ apos_w, const float* __restrict__ rpos_w,
                            const float* __restrict__ apos_b, const float* __restrict__ rpos_b,
                            const float* __restrict__ bcont, const float* __restrict__ bias,
                            float* __restrict__ baseo) {
    int gw = (blockIdx.x * blockDim.x + threadIdx.x) >> 5;
    int lane = threadIdx.x & 31;
    if (gw >= M_) return;
    int b = gw / S_;
    const float* srow = sent + (size_t)gw * H_;
    const float* drow = doc + (size_t)b * H_;
    float acc = 0.f;
    for (int j = lane; j < H_; j += 32) acc += srow[j] * (wcont[j] + drow[j]);
    int ap = apos[gw]; ap = ap < 0 ? 0 : (ap > 50 ? 50 : ap);
    int rp = rpos[gw]; rp = rp < 0 ? 0 : (rp > 4 ? 4 : rp);
    for (int p = lane; p < 50; p += 32)
        acc += apos_table[ap * 50 + p] * apos_w[p] + rpos_table[rp * 50 + p] * rpos_w[p];
    for (int off = 16; off; off >>= 1) acc += __shfl_down_sync(0xffffffffu, acc, off);
    if (lane == 0) baseo[gw] = acc + *bcont + *apos_b + *rpos_b + *bias;
}

// ---------------- novelty scan (persistent; 8 batch rows per block) ------------
__global__ void nov_kernel(const float* __restrict__ sent, const float* __restrict__ WnovT,
                           const float* __restrict__ bnov, const float* __restrict__ baseb,
                           float* __restrict__ out) {
    __shared__ float sum_s[8 * 200];
    __shared__ float st[8 * 200];
    __shared__ float ps[8 * 200];
    __shared__ float gsig[8];
    int tid = threadIdx.x;
    int b0 = blockIdx.x * 8;
    for (int i = tid; i < 1600; i += 256) sum_s[i] = 0.f;
    __syncthreads();
    for (int t = 0; t < S_; t++) {
        for (int i = tid; i < 1600; i += 256) {
            int r = i / 200, j = i % 200;
            st[i] = sent[((size_t)((b0 + r) * S_ + t)) * 200 + j];
        }
        __syncthreads();
        if (tid < 200) {
            float acc[8];
            float bb = bnov[tid];
#pragma unroll
            for (int r = 0; r < 8; r++) acc[r] = bb;
            for (int k = 0; k < 200; k += 4) {
                float w0 = WnovT[(k + 0) * 200 + tid];
                float w1 = WnovT[(k + 1) * 200 + tid];
                float w2 = WnovT[(k + 2) * 200 + tid];
                float w3 = WnovT[(k + 3) * 200 + tid];
#pragma unroll
                for (int r = 0; r < 8; r++) {
                    float4 h4 = *(const float4*)&st[r * 200 + k];
                    acc[r] += w0 * h4.x + w1 * h4.y + w2 * h4.z + w3 * h4.w;
                }
            }
#pragma unroll
            for (int r = 0; r < 8; r++) ps[r * 200 + tid] = acc[r] * tanhf(sum_s[r * 200 + tid]);
        }
        __syncthreads();
        int w = tid >> 5, lane = tid & 31;
        {
            float v = 0.f;
            for (int j = lane; j < 200; j += 32) v += ps[w * 200 + j];
            for (int off = 16; off; off >>= 1) v += __shfl_down_sync(0xffffffffu, v, off);
            if (lane == 0) {
                float logit = baseb[(b0 + w) * S_ + t] - v;
                out[(size_t)(b0 + w) * S_ + t] = logit;
                gsig[w] = 1.f / (1.f + __expf(-logit));
            }
        }
        __syncthreads();
        for (int i = tid; i < 1600; i += 256) {
            int r = i / 200;
            sum_s[i] += st[i] * gsig[r];
        }
        __syncthreads();
    }
}

// ---------------- host launch ----------------
static float* sym_addr(const void* sym) {
    void* p = nullptr;
    cudaGetSymbolAddress(&p, sym);
    return (float*)p;
}

extern "C" void kernel_launch(void* const* d_in, const int* in_sizes, int n_in,
                              void* d_out, int out_size) {
    const float* seq        = (const float*)d_in[0];
    const int*   apos       = (const int*)d_in[1];
    const int*   rpos       = (const int*)d_in[2];
    const int*   length     = (const int*)d_in[3];
    const float* apos_table = (const float*)d_in[4];
    const float* rpos_table = (const float*)d_in[5];
    const float* apos_w     = (const float*)d_in[6];
    const float* apos_b     = (const float*)d_in[7];
    const float* rpos_w     = (const float*)d_in[8];
    const float* rpos_b     = (const float*)d_in[9];
    const float* Wih_f      = (const float*)d_in[10];
    const float* Whh_f      = (const float*)d_in[11];
    const float* bih_f      = (const float*)d_in[12];
    const float* bhh_f      = (const float*)d_in[13];
    const float* Wih_b      = (const float*)d_in[14];
    const float* Whh_b      = (const float*)d_in[15];
    const float* bih_b      = (const float*)d_in[16];
    const float* bhh_b      = (const float*)d_in[17];
    const float* Wsent      = (const float*)d_in[18];
    const float* bsent      = (const float*)d_in[19];
    const float* wcont      = (const float*)d_in[20];
    const float* bcont      = (const float*)d_in[21];
    const float* Wdoc1      = (const float*)d_in[22];
    const float* bdoc1      = (const float*)d_in[23];
    const float* Wdoc2      = (const float*)d_in[24];
    const float* bdoc2      = (const float*)d_in[25];
    const float* Wnov       = (const float*)d_in[26];
    const float* bnov       = (const float*)d_in[27];
    const float* bias       = (const float*)d_in[28];
    float* out = (float*)d_out;

    float* gxf    = sym_addr(g_gxf);
    float* gxb    = sym_addr(g_gxb);
    float* hidden = sym_addr(g_hidden);
    float* sent   = sym_addr(g_sent);
    float* baseb  = sym_addr(g_baseb);
    float* avg    = sym_addr(g_avg);
    float* tmp    = sym_addr(g_tmp);
    float* doc    = sym_addr(g_doc);
    float* whtf   = sym_addr(g_WhhTf);
    float* whtb   = sym_addr(g_WhhTb);
    float* wnt    = sym_addr(g_WnovT);

    // weight transposes (tiny)
    transpose_k<<<(G3_ * H_ + 255) / 256, 256>>>(whtf, Whh_f, G3_, H_);
    transpose_k<<<(G3_ * H_ + 255) / 256, 256>>>(whtb, Whh_b, G3_, H_);
    transpose_k<<<(H_ * H_ + 255) / 256, 256>>>(wnt, Wnov, H_, H_);

    // gx GEMMs: [51200,300] x [300,600]
    dim3 gx_grid(5, 400);
    sgemm_nt<0><<<gx_grid, 256>>>(seq, Wih_f, bih_f, gxf, M_, G3_, E_);
    sgemm_nt<0><<<gx_grid, 256>>>(seq, Wih_b, bih_b, gxb, M_, G3_, E_);

    // recurrence (both directions)
    cudaFuncSetAttribute(gru_kernel, cudaFuncAttributeMaxDynamicSharedMemorySize, 51200);
    gru_kernel<<<dim3(64, 2), 608, 51200>>>(gxf, gxb, whtf, whtb, bhh_f, bhh_b, hidden);

    // sent = relu(hidden @ Wsent^T + bsent): [51200,400] x [400,200]
    sgemm_nt<1><<<dim3(2, 400), 256>>>(hidden, Wsent, bsent, sent, M_, H_, 2 * H_);

    // avg + doc MLP
    avg_kernel<<<(B_ * H_ + 255) / 256, 256>>>(sent, length, avg);
    sgemm_nt<2><<<dim3(2, 8), 256>>>(avg, Wdoc1, bdoc1, tmp, B_, H_, H_);
    sgemm_nt<0><<<dim3(2, 8), 256>>>(tmp, Wdoc2, bdoc2, doc, B_, H_, H_);

    // base logits
    base_kernel<<<M_ / 8, 256>>>(sent, wcont, doc, apos, rpos, apos_table, rpos_table,
                                 apos_w, rpos_w, apos_b, rpos_b, bcont, bias, baseb);

    // novelty scan -> output
    nov_kernel<<<B_ / 8, 256>>>(sent, wnt, bnov, baseb, out);
}

// round 2
// speedup vs baseline: 1.2149x; 1.2149x over previous
#include <cuda_runtime.h>
#include <math.h>

#define B_   1024
#define S_   50
#define E_   300
#define H_   200
#define G3_  600      // 3H
#define M_   (B_*S_)  // 51200

// ---------------- scratch (device globals; no allocations) ----------------
__device__ float g_gxf[(size_t)M_ * G3_];
__device__ float g_gxb[(size_t)M_ * G3_];
__device__ float g_hidden[(size_t)M_ * 2 * H_];
__device__ float g_sent[(size_t)M_ * H_];
__device__ float g_baseb[M_];
__device__ float g_avg[B_ * H_];
__device__ float g_tmp[B_ * H_];
__device__ float g_doc[B_ * H_];
__device__ float g_Wqf[H_ * G3_];   // packed Whh_f: float4 groups
__device__ float g_Wqb[H_ * G3_];   // packed Whh_b
__device__ float g_Wnq[H_ * H_];    // packed Wnov

// ---------------- packed fp32x2 FMA ----------------
__device__ __forceinline__ float2 ffma2(float2 a, float2 b, float2 c) {
    unsigned long long ua = *(unsigned long long*)&a;
    unsigned long long ub = *(unsigned long long*)&b;
    unsigned long long uc = *(unsigned long long*)&c;
    unsigned long long r;
    asm("fma.rn.f32x2 %0, %1, %2, %3;" : "=l"(r) : "l"(ua), "l"(ub), "l"(uc));
    return *(float2*)&r;
}

// ---------------- weight pack: src [G][4*K4] -> dst float4 at [k4*G + g] -----
__global__ void pack_w4(float4* __restrict__ dst, const float* __restrict__ src,
                        int G, int K4) {
    int i = blockIdx.x * blockDim.x + threadIdx.x;
    if (i < G * K4) {
        int k4 = i / G, g = i % G;
        const float* s = src + (size_t)g * (4 * K4) + 4 * k4;
        dst[i] = make_float4(s[0], s[1], s[2], s[3]);
    }
}

// ---------------- SGEMM: C[m,n] = act(sum_k A[m,k]*B[n,k] + bias[n]) ----------
// A: [M,K] row-major; Bm: [N,K] row-major. M % 128 == 0. FFMA2 + double buffer.
template <int ACT>
__global__ void __launch_bounds__(256, 2)
sgemm_nt(const float* __restrict__ A, const float* __restrict__ Bm,
         const float* __restrict__ bias, float* __restrict__ C,
         int M, int N, int K) {
    __shared__ float As[2][8][128];
    __shared__ float Bs[2][8][128];
    int tid = threadIdx.x;
    int tx = tid & 15, ty = tid >> 4;
    int m0 = blockIdx.y * 128, n0 = blockIdx.x * 128;
    int lr = tid >> 1, lq = tid & 1;
    int m = m0 + lr, n = n0 + lr;
    bool nok = (n < N);
    const float* Arow = A + (size_t)m * K;
    const float* Brow = Bm + (size_t)n * K;

    float2 acc[8][4];
#pragma unroll
    for (int i = 0; i < 8; i++)
#pragma unroll
        for (int j = 0; j < 4; j++) acc[i][j] = make_float2(0.f, 0.f);

    float av[4], bv[4];
    auto load_chunk = [&](int k0) {
        int k = k0 + lq * 4;
        if (k + 3 < K) {
            float4 t = *(const float4*)&Arow[k];
            av[0] = t.x; av[1] = t.y; av[2] = t.z; av[3] = t.w;
            if (nok) {
                float4 u = *(const float4*)&Brow[k];
                bv[0] = u.x; bv[1] = u.y; bv[2] = u.z; bv[3] = u.w;
            } else { bv[0] = bv[1] = bv[2] = bv[3] = 0.f; }
        } else {
#pragma unroll
            for (int i = 0; i < 4; i++) {
                av[i] = (k + i < K) ? Arow[k + i] : 0.f;
                bv[i] = (nok && k + i < K) ? Brow[k + i] : 0.f;
            }
        }
    };
    auto store_chunk = [&](int buf) {
#pragma unroll
        for (int i = 0; i < 4; i++) {
            As[buf][lq * 4 + i][lr] = av[i];
            Bs[buf][lq * 4 + i][lr] = bv[i];
        }
    };
    auto compute = [&](int buf) {
#pragma unroll
        for (int kk = 0; kk < 8; kk++) {
            float4 a0 = *(const float4*)&As[buf][kk][ty * 8];
            float4 a1 = *(const float4*)&As[buf][kk][ty * 8 + 4];
            float4 b0 = *(const float4*)&Bs[buf][kk][tx * 8];
            float4 b1 = *(const float4*)&Bs[buf][kk][tx * 8 + 4];
            float a[8] = {a0.x, a0.y, a0.z, a0.w, a1.x, a1.y, a1.z, a1.w};
            float2 b2[4] = {make_float2(b0.x, b0.y), make_float2(b0.z, b0.w),
                            make_float2(b1.x, b1.y), make_float2(b1.z, b1.w)};
#pragma unroll
            for (int i = 0; i < 8; i++) {
                float2 ad = make_float2(a[i], a[i]);
#pragma unroll
                for (int j = 0; j < 4; j++) acc[i][j] = ffma2(ad, b2[j], acc[i][j]);
            }
        }
    };

    int nt = (K + 7) / 8;
    load_chunk(0);
    store_chunk(0);
    __syncthreads();
    int cur = 0;
    for (int t = 1; t < nt; t++) {
        load_chunk(t * 8);
        compute(cur);
        store_chunk(cur ^ 1);
        __syncthreads();
        cur ^= 1;
    }
    compute(cur);

#pragma unroll
    for (int i = 0; i < 8; i++) {
        int mm = m0 + ty * 8 + i;
#pragma unroll
        for (int j = 0; j < 4; j++) {
            int nn = n0 + tx * 8 + j * 2;
            if (nn + 1 < N) {
                float2 v = acc[i][j];
                if (bias) { v.x += bias[nn]; v.y += bias[nn + 1]; }
                if (ACT == 1) { v.x = fmaxf(v.x, 0.f); v.y = fmaxf(v.y, 0.f); }
                if (ACT == 2) { v.x = tanhf(v.x); v.y = tanhf(v.y); }
                *(float2*)&C[(size_t)mm * N + nn] = v;
            } else if (nn < N) {
                float v = acc[i][j].x + (bias ? bias[nn] : 0.f);
                if (ACT == 1) v = fmaxf(v, 0.f);
                if (ACT == 2) v = tanhf(v);
                C[(size_t)mm * N + nn] = v;
            }
        }
    }
}

// ---------------- bidirectional GRU recurrence (persistent per-block) ----------
// grid (64, 2); 16 batch rows per block; 608 threads.
// dyn smem: hs[16][200] + ghs[16][600] = 51200 B
__global__ void __launch_bounds__(608, 1)
gru_kernel(const float* __restrict__ gxf, const float* __restrict__ gxb,
           const float4* __restrict__ Wqf, const float4* __restrict__ Wqb,
           const float* __restrict__ bhhf, const float* __restrict__ bhhb,
           float* __restrict__ hidden) {
    extern __shared__ float sm[];
    float* hs  = sm;             // [16][200]
    float* ghs = sm + 16 * 200;  // [16][600]
    int dir = blockIdx.y;
    const float* gx  = dir ? gxb : gxf;
    const float4* Wq = dir ? Wqb : Wqf;
    const float* bhh = dir ? bhhb : bhhf;
    int b0 = blockIdx.x * 16;
    int tid = threadIdx.x;

    for (int i = tid; i < 16 * 200; i += blockDim.x) hs[i] = 0.f;
    __syncthreads();

    for (int t = 0; t < S_; t++) {
        int s = dir ? (S_ - 1 - t) : t;
        if (tid < 600) {
            float2 acc2[16];
#pragma unroll
            for (int r = 0; r < 16; r++) acc2[r] = make_float2(0.f, 0.f);
            for (int k4 = 0; k4 < 50; k4++) {
                float4 w = Wq[k4 * 600 + tid];
                float2 w01 = make_float2(w.x, w.y);
                float2 w23 = make_float2(w.z, w.w);
#pragma unroll
                for (int r = 0; r < 16; r++) {
                    float4 h4 = *(const float4*)&hs[r * 200 + k4 * 4];
                    acc2[r] = ffma2(w01, make_float2(h4.x, h4.y), acc2[r]);
                    acc2[r] = ffma2(w23, make_float2(h4.z, h4.w), acc2[r]);
                }
            }
            float bb = bhh[tid];
#pragma unroll
            for (int r = 0; r < 16; r++) ghs[r * 600 + tid] = acc2[r].x + acc2[r].y + bb;
        }
        __syncthreads();
        for (int idx = tid; idx < 16 * 200; idx += blockDim.x) {
            int r = idx / 200, j = idx % 200;
            const float* gxr = gx + ((size_t)((b0 + r) * S_ + s)) * 600;
            float gr = ghs[r * 600 + j];
            float gz = ghs[r * 600 + 200 + j];
            float gn = ghs[r * 600 + 400 + j];
            float rg = 1.f / (1.f + __expf(-(gxr[j] + gr)));
            float zg = 1.f / (1.f + __expf(-(gxr[200 + j] + gz)));
            float nn = tanhf(gxr[400 + j] + rg * gn);
            float hprev = hs[r * 200 + j];
            float hnew = (1.f - zg) * nn + zg * hprev;
            hs[r * 200 + j] = hnew;
            hidden[((size_t)((b0 + r) * S_ + s)) * 400 + dir * 200 + j] = hnew;
        }
        __syncthreads();
    }
}

// ---------------- avg over sequence ----------------
__global__ void avg_kernel(const float* __restrict__ sent, const int* __restrict__ length,
                           float* __restrict__ avg) {
    int i = blockIdx.x * blockDim.x + threadIdx.x;
    if (i < B_ * H_) {
        int b = i / H_, h = i % H_;
        float s = 0.f;
        for (int t = 0; t < S_; t++) s += sent[((size_t)(b * S_ + t)) * H_ + h];
        avg[i] = s / (float)length[b];
    }
}

// ---------------- base = content + salience + pos logits + scalars -------------
__global__ void base_kernel(const float* __restrict__ sent, const float* __restrict__ wcont,
                            const float* __restrict__ doc,
                            const int* __restrict__ apos, const int* __restrict__ rpos,
                            const float* __restrict__ apos_table, const float* __restrict__ rpos_table,
                            const float* __restrict__ apos_w, const float* __restrict__ rpos_w,
                            const float* __restrict__ apos_b, const float* __restrict__ rpos_b,
                            const float* __restrict__ bcont, const float* __restrict__ bias,
                            float* __restrict__ baseo) {
    int gw = (blockIdx.x * blockDim.x + threadIdx.x) >> 5;
    int lane = threadIdx.x & 31;
    if (gw >= M_) return;
    int b = gw / S_;
    const float* srow = sent + (size_t)gw * H_;
    const float* drow = doc + (size_t)b * H_;
    float acc = 0.f;
    for (int j = lane; j < H_; j += 32) acc += srow[j] * (wcont[j] + drow[j]);
    int ap = apos[gw]; ap = ap < 0 ? 0 : (ap > 50 ? 50 : ap);
    int rp = rpos[gw]; rp = rp < 0 ? 0 : (rp > 4 ? 4 : rp);
    for (int p = lane; p < 50; p += 32)
        acc += apos_table[ap * 50 + p] * apos_w[p] + rpos_table[rp * 50 + p] * rpos_w[p];
    for (int off = 16; off; off >>= 1) acc += __shfl_down_sync(0xffffffffu, acc, off);
    if (lane == 0) baseo[gw] = acc + *bcont + *apos_b + *rpos_b + *bias;
}

// ---------------- novelty scan (persistent; 8 batch rows per block) ------------
__global__ void __launch_bounds__(256, 1)
nov_kernel(const float* __restrict__ sent, const float4* __restrict__ Wnq,
           const float* __restrict__ bnov, const float* __restrict__ baseb,
           float* __restrict__ out) {
    __shared__ float sum_s[8 * 200];
    __shared__ float st[8 * 200];
    __shared__ float ps[8 * 200];
    __shared__ float gsig[8];
    int tid = threadIdx.x;
    int b0 = blockIdx.x * 8;
    for (int i = tid; i < 1600; i += 256) sum_s[i] = 0.f;
    __syncthreads();
    for (int t = 0; t < S_; t++) {
        for (int i = tid; i < 1600; i += 256) {
            int r = i / 200, j = i % 200;
            st[i] = sent[((size_t)((b0 + r) * S_ + t)) * 200 + j];
        }
        __syncthreads();
        if (tid < 200) {
            float2 acc2[8];
#pragma unroll
            for (int r = 0; r < 8; r++) acc2[r] = make_float2(0.f, 0.f);
            for (int k4 = 0; k4 < 50; k4++) {
                float4 w = Wnq[k4 * 200 + tid];
                float2 w01 = make_float2(w.x, w.y);
                float2 w23 = make_float2(w.z, w.w);
#pragma unroll
                for (int r = 0; r < 8; r++) {
                    float4 h4 = *(const float4*)&st[r * 200 + k4 * 4];
                    acc2[r] = ffma2(w01, make_float2(h4.x, h4.y), acc2[r]);
                    acc2[r] = ffma2(w23, make_float2(h4.z, h4.w), acc2[r]);
                }
            }
            float bb = bnov[tid];
#pragma unroll
            for (int r = 0; r < 8; r++)
                ps[r * 200 + tid] = (acc2[r].x + acc2[r].y + bb) * tanhf(sum_s[r * 200 + tid]);
        }
        __syncthreads();
        int w = tid >> 5, lane = tid & 31;
        {
            float v = 0.f;
            for (int j = lane; j < 200; j += 32) v += ps[w * 200 + j];
            for (int off = 16; off; off >>= 1) v += __shfl_down_sync(0xffffffffu, v, off);
            if (lane == 0) {
                float logit = baseb[(b0 + w) * S_ + t] - v;
                out[(size_t)(b0 + w) * S_ + t] = logit;
                gsig[w] = 1.f / (1.f + __expf(-logit));
            }
        }
        __syncthreads();
        for (int i = tid; i < 1600; i += 256) {
            int r = i / 200;
            sum_s[i] += st[i] * gsig[r];
        }
        __syncthreads();
    }
}

// ---------------- host launch ----------------
static float* sym_addr(const void* sym) {
    void* p = nullptr;
    cudaGetSymbolAddress(&p, sym);
    return (float*)p;
}

extern "C" void kernel_launch(void* const* d_in, const int* in_sizes, int n_in,
                              void* d_out, int out_size) {
    const float* seq        = (const float*)d_in[0];
    const int*   apos       = (const int*)d_in[1];
    const int*   rpos       = (const int*)d_in[2];
    const int*   length     = (const int*)d_in[3];
    const float* apos_table = (const float*)d_in[4];
    const float* rpos_table = (const float*)d_in[5];
    const float* apos_w     = (const float*)d_in[6];
    const float* apos_b     = (const float*)d_in[7];
    const float* rpos_w     = (const float*)d_in[8];
    const float* rpos_b     = (const float*)d_in[9];
    const float* Wih_f      = (const float*)d_in[10];
    const float* Whh_f      = (const float*)d_in[11];
    const float* bih_f      = (const float*)d_in[12];
    const float* bhh_f      = (const float*)d_in[13];
    const float* Wih_b      = (const float*)d_in[14];
    const float* Whh_b      = (const float*)d_in[15];
    const float* bih_b      = (const float*)d_in[16];
    const float* bhh_b      = (const float*)d_in[17];
    const float* Wsent      = (const float*)d_in[18];
    const float* bsent      = (const float*)d_in[19];
    const float* wcont      = (const float*)d_in[20];
    const float* bcont      = (const float*)d_in[21];
    const float* Wdoc1      = (const float*)d_in[22];
    const float* bdoc1      = (const float*)d_in[23];
    const float* Wdoc2      = (const float*)d_in[24];
    const float* bdoc2      = (const float*)d_in[25];
    const float* Wnov       = (const float*)d_in[26];
    const float* bnov       = (const float*)d_in[27];
    const float* bias       = (const float*)d_in[28];
    float* out = (float*)d_out;

    float* gxf    = sym_addr(g_gxf);
    float* gxb    = sym_addr(g_gxb);
    float* hidden = sym_addr(g_hidden);
    float* sent   = sym_addr(g_sent);
    float* baseb  = sym_addr(g_baseb);
    float* avg    = sym_addr(g_avg);
    float* tmp    = sym_addr(g_tmp);
    float* doc    = sym_addr(g_doc);
    float4* wqf   = (float4*)sym_addr(g_Wqf);
    float4* wqb   = (float4*)sym_addr(g_Wqb);
    float4* wnq   = (float4*)sym_addr(g_Wnq);

    // weight packs (tiny)
    pack_w4<<<(G3_ * 50 + 255) / 256, 256>>>(wqf, Whh_f, G3_, 50);
    pack_w4<<<(G3_ * 50 + 255) / 256, 256>>>(wqb, Whh_b, G3_, 50);
    pack_w4<<<(H_ * 50 + 255) / 256, 256>>>(wnq, Wnov, H_, 50);

    // gx GEMMs: [51200,300] x [300,600]
    dim3 gx_grid(5, 400);
    sgemm_nt<0><<<gx_grid, 256>>>(seq, Wih_f, bih_f, gxf, M_, G3_, E_);
    sgemm_nt<0><<<gx_grid, 256>>>(seq, Wih_b, bih_b, gxb, M_, G3_, E_);

    // recurrence (both directions)
    cudaFuncSetAttribute(gru_kernel, cudaFuncAttributeMaxDynamicSharedMemorySize, 51200);
    gru_kernel<<<dim3(64, 2), 608, 51200>>>(gxf, gxb, wqf, wqb, bhh_f, bhh_b, hidden);

    // sent = relu(hidden @ Wsent^T + bsent): [51200,400] x [400,200]
    sgemm_nt<1><<<dim3(2, 400), 256>>>(hidden, Wsent, bsent, sent, M_, H_, 2 * H_);

    // avg + doc MLP
    avg_kernel<<<(B_ * H_ + 255) / 256, 256>>>(sent, length, avg);
    sgemm_nt<2><<<dim3(2, 8), 256>>>(avg, Wdoc1, bdoc1, tmp, B_, H_, H_);
    sgemm_nt<0><<<dim3(2, 8), 256>>>(tmp, Wdoc2, bdoc2, doc, B_, H_, H_);

    // base logits
    base_kernel<<<M_ / 8, 256>>>(sent, wcont, doc, apos, rpos, apos_table, rpos_table,
                                 apos_w, rpos_w, apos_b, rpos_b, bcont, bias, baseb);

    // novelty scan -> output
    nov_kernel<<<B_ / 8, 256>>>(sent, wnq, bnov, baseb, out);
}

// round 4
// speedup vs baseline: 1.4416x; 1.1866x over previous
#include <cuda_runtime.h>
#include <cuda_bf16.h>
#include <math.h>
#include <stdint.h>

#define B_   1024
#define S_   50
#define E_   300
#define H_   200
#define M_   51200
#define NGX  1200          // stacked f|b gate width
#define KP_GX   320        // K=300 padded
#define KP_SENT 416        // K=400 padded (needs %32)
#define NP_GX   1280       // N=1200 padded to tile
#define NP_SENT 256        // N=200 padded to tile

// ---------------- scratch (device globals; no allocations) ----------------
__device__ __align__(256) __nv_bfloat16 g_Ahi[(size_t)M_ * KP_GX];
__device__ __align__(256) __nv_bfloat16 g_Alo[(size_t)M_ * KP_GX];
__device__ __align__(256) __nv_bfloat16 g_Hhi[(size_t)M_ * KP_SENT];
__device__ __align__(256) __nv_bfloat16 g_Hlo[(size_t)M_ * KP_SENT];
__device__ __align__(256) __nv_bfloat16 g_Bgxhi[(size_t)NP_GX * KP_GX];
__device__ __align__(256) __nv_bfloat16 g_Bgxlo[(size_t)NP_GX * KP_GX];
__device__ __align__(256) __nv_bfloat16 g_Bsehi[(size_t)NP_SENT * KP_SENT];
__device__ __align__(256) __nv_bfloat16 g_Bselo[(size_t)NP_SENT * KP_SENT];
__device__ float g_gx[(size_t)M_ * NGX];
__device__ float g_hidden[(size_t)M_ * 2 * H_];
__device__ float g_sent[(size_t)M_ * H_];
__device__ float g_baseb[M_];
__device__ float g_avg[B_ * H_];
__device__ float g_tmp[B_ * H_];
__device__ float g_doc[B_ * H_];
__device__ float g_Wqf[H_ * 3 * H_];
__device__ float g_Wqb[H_ * 3 * H_];
__device__ float g_Wnq[H_ * H_];

// ---------------- helpers ----------------
__device__ __forceinline__ uint32_t smem_u32(const void* p) {
    uint32_t a;
    asm("{ .reg .u64 t; cvta.to.shared.u64 t, %1; cvt.u32.u64 %0, t; }" : "=r"(a) : "l"(p));
    return a;
}
__device__ __forceinline__ void ldm4(uint32_t* r, uint32_t addr) {
    asm volatile("ldmatrix.sync.aligned.m8n8.x4.shared.b16 {%0,%1,%2,%3}, [%4];"
        : "=r"(r[0]), "=r"(r[1]), "=r"(r[2]), "=r"(r[3]) : "r"(addr));
}
__device__ __forceinline__ void mma_bf16(float* c, const uint32_t* a, const uint32_t* b) {
    asm volatile(
        "mma.sync.aligned.m16n8k16.row.col.f32.bf16.bf16.f32 "
        "{%0,%1,%2,%3}, {%4,%5,%6,%7}, {%8,%9}, {%0,%1,%2,%3};"
        : "+f"(c[0]), "+f"(c[1]), "+f"(c[2]), "+f"(c[3])
        : "r"(a[0]), "r"(a[1]), "r"(a[2]), "r"(a[3]), "r"(b[0]), "r"(b[1]));
}
__device__ __forceinline__ float2 ffma2(float2 a, float2 b, float2 c) {
    unsigned long long ua = *(unsigned long long*)&a;
    unsigned long long ub = *(unsigned long long*)&b;
    unsigned long long uc = *(unsigned long long*)&c;
    unsigned long long r;
    asm("fma.rn.f32x2 %0, %1, %2, %3;" : "=l"(r) : "l"(ua), "l"(ub), "l"(uc));
    return *(float2*)&r;
}

// ---------------- fp32 -> bf16 hi/lo conversion (rows0|rows1 stacked, zero pad) ----
__global__ void conv_hilo(const float* __restrict__ X0, const float* __restrict__ X1,
                          int rows0, int rows1, int K, int Kpad, int totalRows,
                          __nv_bfloat16* __restrict__ hi, __nv_bfloat16* __restrict__ lo) {
    int i = blockIdx.x * blockDim.x + threadIdx.x;
    if (i >= totalRows * Kpad) return;
    int row = i / Kpad, k = i - row * Kpad;
    float x = 0.f;
    if (k < K) {
        if (row < rows0) x = X0[(size_t)row * K + k];
        else if (X1 && row < rows0 + rows1) x = X1[(size_t)(row - rows0) * K + k];
    }
    __nv_bfloat16 h = __float2bfloat16(x);
    float res = x - __bfloat162float(h);
    hi[i] = h;
    lo[i] = __float2bfloat16(res);
}

// ---------------- split-bf16 tensor-core GEMM (mma.sync) -----------------------
// C[m,n] = act( sum_k A[m,k]*B[n,k] + bias[n] ), A:[M][Kpad] bf16 hi/lo, B:[Npad][Kpad].
// 256 threads = 8 warps (4m x 2n), CTA tile 128x128, BK=32, cp.async double buffer.
// smem mat: 128 rows x pitch 40 bf16 (80B rows -> ldmatrix conflict-free).
#define MMA_SMEM (2 * 4 * 10240)

template <int ACT>
__global__ void __launch_bounds__(256, 1)
mma_gemm(const __nv_bfloat16* __restrict__ Ahi, const __nv_bfloat16* __restrict__ Alo,
         const __nv_bfloat16* __restrict__ Bhi, const __nv_bfloat16* __restrict__ Blo,
         const float* __restrict__ bias0, const float* __restrict__ bias1, int nsplit,
         float* __restrict__ C, int ldc, int Nvalid, int Kpad) {
    extern __shared__ __align__(16) __nv_bfloat16 smbuf[];
    uint32_t sb = smem_u32(smbuf);
    int tid = threadIdx.x;
    int w = tid >> 5, lane = tid & 31;
    int wm = (w >> 1) * 32, wn = (w & 1) * 64;
    int m0 = blockIdx.y * 128, n0 = blockIdx.x * 128;

    const __nv_bfloat16* gsrc0 = Ahi + (size_t)m0 * Kpad;
    const __nv_bfloat16* gsrc1 = Alo + (size_t)m0 * Kpad;
    const __nv_bfloat16* gsrc2 = Bhi + (size_t)n0 * Kpad;
    const __nv_bfloat16* gsrc3 = Blo + (size_t)n0 * Kpad;

    float acc[2][8][4];
#pragma unroll
    for (int i = 0; i < 2; i++)
#pragma unroll
        for (int j = 0; j < 8; j++)
#pragma unroll
            for (int e = 0; e < 4; e++) acc[i][j][e] = 0.f;

    int rowA = ((lane >> 3) & 1) * 8 + (lane & 7);
    int kA   = ((lane >> 4) & 1) * 8;
    int rowB = ((lane >> 4) & 1) * 8 + (lane & 7);
    int kB   = ((lane >> 3) & 1) * 8;

    int nstages = Kpad / 32;
    auto load_stage = [&](int s) {
        int buf = s & 1;
        int k0 = s * 32;
#pragma unroll
        for (int i = 0; i < 8; i++) {
            int t = tid + i * 256;        // 0..2047
            int mat = t >> 9;             // 0..3
            int c = t & 511;
            int row = c >> 2, kc = c & 3;
            uint32_t dst = sb + buf * 40960 + mat * 10240 + row * 80 + kc * 16;
            const __nv_bfloat16* src =
                (mat == 0 ? gsrc0 : mat == 1 ? gsrc1 : mat == 2 ? gsrc2 : gsrc3)
                + (size_t)row * Kpad + k0 + kc * 8;
            asm volatile("cp.async.cg.shared.global [%0], [%1], 16;" :: "r"(dst), "l"(src));
        }
        asm volatile("cp.async.commit_group;");
    };

    load_stage(0);
    for (int s = 0; s < nstages; s++) {
        if (s + 1 < nstages) {
            load_stage(s + 1);
            asm volatile("cp.async.wait_group 1;");
        } else {
            asm volatile("cp.async.wait_group 0;");
        }
        __syncthreads();
        uint32_t base = sb + (s & 1) * 40960;
#pragma unroll
        for (int k16 = 0; k16 < 32; k16 += 16) {
            uint32_t ah[2][4], alr[2][4];
#pragma unroll
            for (int ma = 0; ma < 2; ma++) {
                uint32_t off = (uint32_t)(((wm + ma * 16 + rowA) * 40 + k16 + kA) * 2);
                ldm4(ah[ma], base + off);
                ldm4(alr[ma], base + 10240 + off);
            }
            uint32_t bh[4][4], blr[4][4];
#pragma unroll
            for (int nb = 0; nb < 4; nb++) {
                uint32_t off = (uint32_t)(((wn + nb * 16 + rowB) * 40 + k16 + kB) * 2);
                ldm4(bh[nb], base + 20480 + off);
                ldm4(blr[nb], base + 30720 + off);
            }
#pragma unroll
            for (int ma = 0; ma < 2; ma++)
#pragma unroll
                for (int na = 0; na < 8; na++)
                    mma_bf16(acc[ma][na], ah[ma], &bh[na >> 1][(na & 1) * 2]);
#pragma unroll
            for (int ma = 0; ma < 2; ma++)
#pragma unroll
                for (int na = 0; na < 8; na++)
                    mma_bf16(acc[ma][na], ah[ma], &blr[na >> 1][(na & 1) * 2]);
#pragma unroll
            for (int ma = 0; ma < 2; ma++)
#pragma unroll
                for (int na = 0; na < 8; na++)
                    mma_bf16(acc[ma][na], alr[ma], &bh[na >> 1][(na & 1) * 2]);
        }
        __syncthreads();
    }

    // epilogue: c0,c1 at (row=lane/4, col=(lane%4)*2), c2,c3 at row+8
    int r0 = m0 + wm + (lane >> 2);
    int cb = n0 + wn + (lane & 3) * 2;
#pragma unroll
    for (int ma = 0; ma < 2; ma++) {
        int r = r0 + ma * 16;
#pragma unroll
        for (int na = 0; na < 8; na++) {
            int col = cb + na * 8;
            if (col < Nvalid) {
                float b0v = (col < nsplit) ? bias0[col] : bias1[col - nsplit];
                float b1v = (col + 1 < nsplit) ? bias0[col + 1] : bias1[col + 1 - nsplit];
                float2 v0 = make_float2(acc[ma][na][0] + b0v, acc[ma][na][1] + b1v);
                float2 v1 = make_float2(acc[ma][na][2] + b0v, acc[ma][na][3] + b1v);
                if (ACT == 1) {
                    v0.x = fmaxf(v0.x, 0.f); v0.y = fmaxf(v0.y, 0.f);
                    v1.x = fmaxf(v1.x, 0.f); v1.y = fmaxf(v1.y, 0.f);
                }
                *(float2*)&C[(size_t)r * ldc + col] = v0;
                *(float2*)&C[(size_t)(r + 8) * ldc + col] = v1;
            }
        }
    }
}

// ---------------- weight pack for scans ----------------
__global__ void pack_w4(float4* __restrict__ dst, const float* __restrict__ src,
                        int G, int K4) {
    int i = blockIdx.x * blockDim.x + threadIdx.x;
    if (i < G * K4) {
        int k4 = i / G, g = i % G;
        const float* s = src + (size_t)g * (4 * K4) + 4 * k4;
        dst[i] = make_float4(s[0], s[1], s[2], s[3]);
    }
}

// ---------------- small fp32 SGEMM (doc MLP only) ----------------
template <int ACT>
__global__ void __launch_bounds__(256, 2)
sgemm_nt(const float* __restrict__ A, const float* __restrict__ Bm,
         const float* __restrict__ bias, float* __restrict__ C,
         int M, int N, int K) {
    __shared__ float As[2][8][128];
    __shared__ float Bs[2][8][128];
    int tid = threadIdx.x;
    int tx = tid & 15, ty = tid >> 4;
    int m0 = blockIdx.y * 128, n0 = blockIdx.x * 128;
    int lr = tid >> 1, lq = tid & 1;
    int m = m0 + lr, n = n0 + lr;
    bool nok = (n < N);
    const float* Arow = A + (size_t)m * K;
    const float* Brow = Bm + (size_t)n * K;
    float2 acc[8][4];
#pragma unroll
    for (int i = 0; i < 8; i++)
#pragma unroll
        for (int j = 0; j < 4; j++) acc[i][j] = make_float2(0.f, 0.f);
    float av[4], bv[4];
    auto load_chunk = [&](int k0) {
        int k = k0 + lq * 4;
#pragma unroll
        for (int i = 0; i < 4; i++) {
            av[i] = (k + i < K) ? Arow[k + i] : 0.f;
            bv[i] = (nok && k + i < K) ? Brow[k + i] : 0.f;
        }
    };
    auto store_chunk = [&](int buf) {
#pragma unroll
        for (int i = 0; i < 4; i++) {
            As[buf][lq * 4 + i][lr] = av[i];
            Bs[buf][lq * 4 + i][lr] = bv[i];
        }
    };
    auto compute = [&](int buf) {
#pragma unroll
        for (int kk = 0; kk < 8; kk++) {
            float4 a0 = *(const float4*)&As[buf][kk][ty * 8];
            float4 a1 = *(const float4*)&As[buf][kk][ty * 8 + 4];
            float4 b0 = *(const float4*)&Bs[buf][kk][tx * 8];
            float4 b1 = *(const float4*)&Bs[buf][kk][tx * 8 + 4];
            float a[8] = {a0.x, a0.y, a0.z, a0.w, a1.x, a1.y, a1.z, a1.w};
            float2 b2[4] = {make_float2(b0.x, b0.y), make_float2(b0.z, b0.w),
                            make_float2(b1.x, b1.y), make_float2(b1.z, b1.w)};
#pragma unroll
            for (int i = 0; i < 8; i++) {
                float2 ad = make_float2(a[i], a[i]);
#pragma unroll
                for (int j = 0; j < 4; j++) acc[i][j] = ffma2(ad, b2[j], acc[i][j]);
            }
        }
    };
    int nt = (K + 7) / 8;
    load_chunk(0);
    store_chunk(0);
    __syncthreads();
    int cur = 0;
    for (int t = 1; t < nt; t++) {
        load_chunk(t * 8);
        compute(cur);
        store_chunk(cur ^ 1);
        __syncthreads();
        cur ^= 1;
    }
    compute(cur);
#pragma unroll
    for (int i = 0; i < 8; i++) {
        int mm = m0 + ty * 8 + i;
#pragma unroll
        for (int j = 0; j < 4; j++) {
            int nn = n0 + tx * 8 + j * 2;
            if (nn + 1 < N) {
                float2 v = acc[i][j];
                if (bias) { v.x += bias[nn]; v.y += bias[nn + 1]; }
                if (ACT == 1) { v.x = fmaxf(v.x, 0.f); v.y = fmaxf(v.y, 0.f); }
                if (ACT == 2) { v.x = tanhf(v.x); v.y = tanhf(v.y); }
                *(float2*)&C[(size_t)mm * N + nn] = v;
            } else if (nn < N) {
                float v = acc[i][j].x + (bias ? bias[nn] : 0.f);
                if (ACT == 1) v = fmaxf(v, 0.f);
                if (ACT == 2) v = tanhf(v);
                C[(size_t)mm * N + nn] = v;
            }
        }
    }
}

// ---------------- bidirectional GRU recurrence (persistent) --------------------
__global__ void __launch_bounds__(608, 1)
gru_kernel(const float* __restrict__ gx,
           const float4* __restrict__ Wqf, const float4* __restrict__ Wqb,
           const float* __restrict__ bhhf, const float* __restrict__ bhhb,
           float* __restrict__ hidden) {
    extern __shared__ float sm[];
    float* hs  = sm;             // [16][200]
    float* ghs = sm + 16 * 200;  // [16][600]
    int dir = blockIdx.y;
    const float4* Wq = dir ? Wqb : Wqf;
    const float* bhh = dir ? bhhb : bhhf;
    int b0 = blockIdx.x * 16;
    int tid = threadIdx.x;

    for (int i = tid; i < 16 * 200; i += blockDim.x) hs[i] = 0.f;
    __syncthreads();

    for (int t = 0; t < S_; t++) {
        int s = dir ? (S_ - 1 - t) : t;
        if (tid < 600) {
            float2 acc2[16];
#pragma unroll
            for (int r = 0; r < 16; r++) acc2[r] = make_float2(0.f, 0.f);
            for (int k4 = 0; k4 < 50; k4++) {
                float4 w = Wq[k4 * 600 + tid];
                float2 w01 = make_float2(w.x, w.y);
                float2 w23 = make_float2(w.z, w.w);
#pragma unroll
                for (int r = 0; r < 16; r++) {
                    float4 h4 = *(const float4*)&hs[r * 200 + k4 * 4];
                    acc2[r] = ffma2(w01, make_float2(h4.x, h4.y), acc2[r]);
                    acc2[r] = ffma2(w23, make_float2(h4.z, h4.w), acc2[r]);
                }
            }
            float bb = bhh[tid];
#pragma unroll
            for (int r = 0; r < 16; r++) ghs[r * 600 + tid] = acc2[r].x + acc2[r].y + bb;
        }
        __syncthreads();
        for (int idx = tid; idx < 16 * 200; idx += blockDim.x) {
            int r = idx / 200, j = idx % 200;
            const float* gxr = gx + (size_t)((b0 + r) * S_ + s) * NGX + dir * 600;
            float gr = ghs[r * 600 + j];
            float gz = ghs[r * 600 + 200 + j];
            float gn = ghs[r * 600 + 400 + j];
            float rg = 1.f / (1.f + __expf(-(gxr[j] + gr)));
            float zg = 1.f / (1.f + __expf(-(gxr[200 + j] + gz)));
            float nn = tanhf(gxr[400 + j] + rg * gn);
            float hprev = hs[r * 200 + j];
            float hnew = (1.f - zg) * nn + zg * hprev;
            hs[r * 200 + j] = hnew;
            hidden[((size_t)((b0 + r) * S_ + s)) * 400 + dir * 200 + j] = hnew;
        }
        __syncthreads();
    }
}

// ---------------- avg over sequence ----------------
__global__ void avg_kernel(const float* __restrict__ sent, const int* __restrict__ length,
                           float* __restrict__ avg) {
    int i = blockIdx.x * blockDim.x + threadIdx.x;
    if (i < B_ * H_) {
        int b = i / H_, h = i % H_;
        float s = 0.f;
        for (int t = 0; t < S_; t++) s += sent[((size_t)(b * S_ + t)) * H_ + h];
        avg[i] = s / (float)length[b];
    }
}

// ---------------- base logits ----------------
__global__ void base_kernel(const float* __restrict__ sent, const float* __restrict__ wcont,
                            const float* __restrict__ doc,
                            const int* __restrict__ apos, const int* __restrict__ rpos,
                            const float* __restrict__ apos_table, const float* __restrict__ rpos_table,
                            const float* __restrict__ apos_w, const float* __restrict__ rpos_w,
                            const float* __restrict__ apos_b, const float* __restrict__ rpos_b,
                            const float* __restrict__ bcont, const float* __restrict__ bias,
                            float* __restrict__ baseo) {
    int gw = (blockIdx.x * blockDim.x + threadIdx.x) >> 5;
    int lane = threadIdx.x & 31;
    if (gw >= M_) return;
    int b = gw / S_;
    const float* srow = sent + (size_t)gw * H_;
    const float* drow = doc + (size_t)b * H_;
    float acc = 0.f;
    for (int j = lane; j < H_; j += 32) acc += srow[j] * (wcont[j] + drow[j]);
    int ap = apos[gw]; ap = ap < 0 ? 0 : (ap > 50 ? 50 : ap);
    int rp = rpos[gw]; rp = rp < 0 ? 0 : (rp > 4 ? 4 : rp);
    for (int p = lane; p < 50; p += 32)
        acc += apos_table[ap * 50 + p] * apos_w[p] + rpos_table[rp * 50 + p] * rpos_w[p];
    for (int off = 16; off; off >>= 1) acc += __shfl_down_sync(0xffffffffu, acc, off);
    if (lane == 0) baseo[gw] = acc + *bcont + *apos_b + *rpos_b + *bias;
}

// ---------------- novelty scan ----------------
__global__ void __launch_bounds__(256, 1)
nov_kernel(const float* __restrict__ sent, const float4* __restrict__ Wnq,
           const float* __restrict__ bnov, const float* __restrict__ baseb,
           float* __restrict__ out) {
    __shared__ float sum_s[8 * 200];
    __shared__ float st[8 * 200];
    __shared__ float ps[8 * 200];
    __shared__ float gsig[8];
    int tid = threadIdx.x;
    int b0 = blockIdx.x * 8;
    for (int i = tid; i < 1600; i += 256) sum_s[i] = 0.f;
    __syncthreads();
    for (int t = 0; t < S_; t++) {
        for (int i = tid; i < 1600; i += 256) {
            int r = i / 200, j = i % 200;
            st[i] = sent[((size_t)((b0 + r) * S_ + t)) * 200 + j];
        }
        __syncthreads();
        if (tid < 200) {
            float2 acc2[8];
#pragma unroll
            for (int r = 0; r < 8; r++) acc2[r] = make_float2(0.f, 0.f);
            for (int k4 = 0; k4 < 50; k4++) {
                float4 w = Wnq[k4 * 200 + tid];
                float2 w01 = make_float2(w.x, w.y);
                float2 w23 = make_float2(w.z, w.w);
#pragma unroll
                for (int r = 0; r < 8; r++) {
                    float4 h4 = *(const float4*)&st[r * 200 + k4 * 4];
                    acc2[r] = ffma2(w01, make_float2(h4.x, h4.y), acc2[r]);
                    acc2[r] = ffma2(w23, make_float2(h4.z, h4.w), acc2[r]);
                }
            }
            float bb = bnov[tid];
#pragma unroll
            for (int r = 0; r < 8; r++)
                ps[r * 200 + tid] = (acc2[r].x + acc2[r].y + bb) * tanhf(sum_s[r * 200 + tid]);
        }
        __syncthreads();
        int w = tid >> 5, lane = tid & 31;
        {
            float v = 0.f;
            for (int j = lane; j < 200; j += 32) v += ps[w * 200 + j];
            for (int off = 16; off; off >>= 1) v += __shfl_down_sync(0xffffffffu, v, off);
            if (lane == 0) {
                float logit = baseb[(b0 + w) * S_ + t] - v;
                out[(size_t)(b0 + w) * S_ + t] = logit;
                gsig[w] = 1.f / (1.f + __expf(-logit));
            }
        }
        __syncthreads();
        for (int i = tid; i < 1600; i += 256) {
            int r = i / 200;
            sum_s[i] += st[i] * gsig[r];
        }
        __syncthreads();
    }
}

// ---------------- host launch ----------------
static float* sym_addr(const void* sym) {
    void* p = nullptr;
    cudaGetSymbolAddress(&p, sym);
    return (float*)p;
}

extern "C" void kernel_launch(void* const* d_in, const int* in_sizes, int n_in,
                              void* d_out, int out_size) {
    const float* seq        = (const float*)d_in[0];
    const int*   apos       = (const int*)d_in[1];
    const int*   rpos       = (const int*)d_in[2];
    const int*   length     = (const int*)d_in[3];
    const float* apos_table = (const float*)d_in[4];
    const float* rpos_table = (const float*)d_in[5];
    const float* apos_w     = (const float*)d_in[6];
    const float* apos_b     = (const float*)d_in[7];
    const float* rpos_w     = (const float*)d_in[8];
    const float* rpos_b     = (const float*)d_in[9];
    const float* Wih_f      = (const float*)d_in[10];
    const float* Whh_f      = (const float*)d_in[11];
    const float* bih_f      = (const float*)d_in[12];
    const float* bhh_f      = (const float*)d_in[13];
    const float* Wih_b      = (const float*)d_in[14];
    const float* Whh_b      = (const float*)d_in[15];
    const float* bih_b      = (const float*)d_in[16];
    const float* bhh_b      = (const float*)d_in[17];
    const float* Wsent      = (const float*)d_in[18];
    const float* bsent      = (const float*)d_in[19];
    const float* wcont      = (const float*)d_in[20];
    const float* bcont      = (const float*)d_in[21];
    const float* Wdoc1      = (const float*)d_in[22];
    const float* bdoc1      = (const float*)d_in[23];
    const float* Wdoc2      = (const float*)d_in[24];
    const float* bdoc2      = (const float*)d_in[25];
    const float* Wnov       = (const float*)d_in[26];
    const float* bnov       = (const float*)d_in[27];
    const float* bias       = (const float*)d_in[28];
    float* out = (float*)d_out;

    float* gx     = sym_addr(g_gx);
    float* hidden = sym_addr(g_hidden);
    float* sent   = sym_addr(g_sent);
    float* baseb  = sym_addr(g_baseb);
    float* avg    = sym_addr(g_avg);
    float* tmp    = sym_addr(g_tmp);
    float* doc    = sym_addr(g_doc);
    float4* wqf   = (float4*)sym_addr(g_Wqf);
    float4* wqb   = (float4*)sym_addr(g_Wqb);
    float4* wnq   = (float4*)sym_addr(g_Wnq);
    __nv_bfloat16* Ahi = (__nv_bfloat16*)sym_addr(g_Ahi);
    __nv_bfloat16* Alo = (__nv_bfloat16*)sym_addr(g_Alo);
    __nv_bfloat16* Hhi = (__nv_bfloat16*)sym_addr(g_Hhi);
    __nv_bfloat16* Hlo = (__nv_bfloat16*)sym_addr(g_Hlo);
    __nv_bfloat16* Bgxhi = (__nv_bfloat16*)sym_addr(g_Bgxhi);
    __nv_bfloat16* Bgxlo = (__nv_bfloat16*)sym_addr(g_Bgxlo);
    __nv_bfloat16* Bsehi = (__nv_bfloat16*)sym_addr(g_Bsehi);
    __nv_bfloat16* Bselo = (__nv_bfloat16*)sym_addr(g_Bselo);

    cudaFuncSetAttribute(mma_gemm<0>, cudaFuncAttributeMaxDynamicSharedMemorySize, MMA_SMEM);
    cudaFuncSetAttribute(mma_gemm<1>, cudaFuncAttributeMaxDynamicSharedMemorySize, MMA_SMEM);
    cudaFuncSetAttribute(gru_kernel, cudaFuncAttributeMaxDynamicSharedMemorySize, 51200);

    // scan-weight packs (tiny)
    pack_w4<<<(600 * 50 + 255) / 256, 256>>>(wqf, Whh_f, 600, 50);
    pack_w4<<<(600 * 50 + 255) / 256, 256>>>(wqb, Whh_b, 600, 50);
    pack_w4<<<(200 * 50 + 255) / 256, 256>>>(wnq, Wnov, 200, 50);

    // operand conversions to bf16 hi/lo
    conv_hilo<<<((size_t)NP_GX * KP_GX + 255) / 256, 256>>>(
        Wih_f, Wih_b, 600, 600, E_, KP_GX, NP_GX, Bgxhi, Bgxlo);
    conv_hilo<<<((size_t)NP_SENT * KP_SENT + 255) / 256, 256>>>(
        Wsent, nullptr, 200, 0, 2 * H_, KP_SENT, NP_SENT, Bsehi, Bselo);
    conv_hilo<<<((size_t)M_ * KP_GX + 255) / 256, 256>>>(
        seq, nullptr, M_, 0, E_, KP_GX, M_, Ahi, Alo);

    // combined gx GEMM: [51200,1200] = seq @ [Wih_f|Wih_b]^T + bias
    mma_gemm<0><<<dim3(NP_GX / 128, M_ / 128), 256, MMA_SMEM>>>(
        Ahi, Alo, Bgxhi, Bgxlo, bih_f, bih_b, 600, gx, NGX, NGX, KP_GX);

    // recurrence (both directions)
    gru_kernel<<<dim3(64, 2), 608, 51200>>>(gx, wqf, wqb, bhh_f, bhh_b, hidden);

    // sent = relu(hidden @ Wsent^T + bsent)
    conv_hilo<<<((size_t)M_ * KP_SENT + 255) / 256, 256>>>(
        hidden, nullptr, M_, 0, 2 * H_, KP_SENT, M_, Hhi, Hlo);
    mma_gemm<1><<<dim3(NP_SENT / 128, M_ / 128), 256, MMA_SMEM>>>(
        Hhi, Hlo, Bsehi, Bselo, bsent, bsent, H_, sent, H_, H_, KP_SENT);

    // avg + doc MLP (small fp32 path)
    avg_kernel<<<(B_ * H_ + 255) / 256, 256>>>(sent, length, avg);
    sgemm_nt<2><<<dim3(2, 8), 256>>>(avg, Wdoc1, bdoc1, tmp, B_, H_, H_);
    sgemm_nt<0><<<dim3(2, 8), 256>>>(tmp, Wdoc2, bdoc2, doc, B_, H_, H_);

    // base logits
    base_kernel<<<M_ / 8, 256>>>(sent, wcont, doc, apos, rpos, apos_table, rpos_table,
                                 apos_w, rpos_w, apos_b, rpos_b, bcont, bias, baseb);

    // novelty scan -> output
    nov_kernel<<<B_ / 8, 256>>>(sent, wnq, bnov, baseb, out);
}

// round 5
// speedup vs baseline: 1.7378x; 1.2055x over previous
#include <cuda_runtime.h>
#include <cuda_bf16.h>
#include <math.h>
#include <stdint.h>

#define B_   1024
#define S_   50
#define E_   300
#define H_   200
#define M_   51200
#define NGX  1200          // stacked f|b gate width
#define KP_GX   320        // K=300 padded
#define KP_SENT 416        // K=400 padded
#define NP_GX   1280
#define NP_SENT 256
#define GRU_ROWS 14
#define NOV_ROWS 7

// ---------------- scratch (device globals; no allocations) ----------------
__device__ __align__(256) __nv_bfloat16 g_Ahi[(size_t)M_ * KP_GX];
__device__ __align__(256) __nv_bfloat16 g_Alo[(size_t)M_ * KP_GX];
__device__ __align__(256) __nv_bfloat16 g_Hhi[(size_t)M_ * KP_SENT];  // pad cols stay 0
__device__ __align__(256) __nv_bfloat16 g_Hlo[(size_t)M_ * KP_SENT];
__device__ __align__(256) __nv_bfloat16 g_Bgxhi[(size_t)NP_GX * KP_GX];
__device__ __align__(256) __nv_bfloat16 g_Bgxlo[(size_t)NP_GX * KP_GX];
__device__ __align__(256) __nv_bfloat16 g_Bsehi[(size_t)NP_SENT * KP_SENT];
__device__ __align__(256) __nv_bfloat16 g_Bselo[(size_t)NP_SENT * KP_SENT];
__device__ float g_gx[(size_t)M_ * NGX];
__device__ float g_sent[(size_t)M_ * H_];
__device__ float g_avg[B_ * H_];
__device__ float g_tmp[B_ * H_];
__device__ float g_doc[B_ * H_];
__device__ float g_Wqf[H_ * 3 * H_];
__device__ float g_Wqb[H_ * 3 * H_];
__device__ float g_Wnq[H_ * H_];

// ---------------- helpers ----------------
__device__ __forceinline__ uint32_t smem_u32(const void* p) {
    uint32_t a;
    asm("{ .reg .u64 t; cvta.to.shared.u64 t, %1; cvt.u32.u64 %0, t; }" : "=r"(a) : "l"(p));
    return a;
}
__device__ __forceinline__ void ldm4(uint32_t* r, uint32_t addr) {
    asm volatile("ldmatrix.sync.aligned.m8n8.x4.shared.b16 {%0,%1,%2,%3}, [%4];"
        : "=r"(r[0]), "=r"(r[1]), "=r"(r[2]), "=r"(r[3]) : "r"(addr));
}
__device__ __forceinline__ void mma_bf16(float* c, const uint32_t* a, const uint32_t* b) {
    asm volatile(
        "mma.sync.aligned.m16n8k16.row.col.f32.bf16.bf16.f32 "
        "{%0,%1,%2,%3}, {%4,%5,%6,%7}, {%8,%9}, {%0,%1,%2,%3};"
        : "+f"(c[0]), "+f"(c[1]), "+f"(c[2]), "+f"(c[3])
        : "r"(a[0]), "r"(a[1]), "r"(a[2]), "r"(a[3]), "r"(b[0]), "r"(b[1]));
}
__device__ __forceinline__ float2 ffma2(float2 a, float2 b, float2 c) {
    unsigned long long ua = *(unsigned long long*)&a;
    unsigned long long ub = *(unsigned long long*)&b;
    unsigned long long uc = *(unsigned long long*)&c;
    unsigned long long r;
    asm("fma.rn.f32x2 %0, %1, %2, %3;" : "=l"(r) : "l"(ua), "l"(ub), "l"(uc));
    return *(float2*)&r;
}

// ---------------- fp32 -> bf16 hi/lo conversion ----------------
__global__ void conv_hilo(const float* __restrict__ X0, const float* __restrict__ X1,
                          int rows0, int rows1, int K, int Kpad, int totalRows,
                          __nv_bfloat16* __restrict__ hi, __nv_bfloat16* __restrict__ lo) {
    int i = blockIdx.x * blockDim.x + threadIdx.x;
    if (i >= totalRows * Kpad) return;
    int row = i / Kpad, k = i - row * Kpad;
    float x = 0.f;
    if (k < K) {
        if (row < rows0) x = X0[(size_t)row * K + k];
        else if (X1 && row < rows0 + rows1) x = X1[(size_t)(row - rows0) * K + k];
    }
    __nv_bfloat16 h = __float2bfloat16(x);
    float res = x - __bfloat162float(h);
    hi[i] = h;
    lo[i] = __float2bfloat16(res);
}

// ---------------- split-bf16 tensor-core GEMM (mma.sync) -----------------------
#define MMA_SMEM (2 * 4 * 10240)

template <int ACT>
__global__ void __launch_bounds__(256, 1)
mma_gemm(const __nv_bfloat16* __restrict__ Ahi, const __nv_bfloat16* __restrict__ Alo,
         const __nv_bfloat16* __restrict__ Bhi, const __nv_bfloat16* __restrict__ Blo,
         const float* __restrict__ bias0, const float* __restrict__ bias1, int nsplit,
         float* __restrict__ C, int ldc, int Nvalid, int Kpad) {
    extern __shared__ __align__(16) __nv_bfloat16 smbuf[];
    uint32_t sb = smem_u32(smbuf);
    int tid = threadIdx.x;
    int w = tid >> 5, lane = tid & 31;
    int wm = (w >> 1) * 32, wn = (w & 1) * 64;
    int m0 = blockIdx.y * 128, n0 = blockIdx.x * 128;

    const __nv_bfloat16* gsrc0 = Ahi + (size_t)m0 * Kpad;
    const __nv_bfloat16* gsrc1 = Alo + (size_t)m0 * Kpad;
    const __nv_bfloat16* gsrc2 = Bhi + (size_t)n0 * Kpad;
    const __nv_bfloat16* gsrc3 = Blo + (size_t)n0 * Kpad;

    float acc[2][8][4];
#pragma unroll
    for (int i = 0; i < 2; i++)
#pragma unroll
        for (int j = 0; j < 8; j++)
#pragma unroll
            for (int e = 0; e < 4; e++) acc[i][j][e] = 0.f;

    int rowA = ((lane >> 3) & 1) * 8 + (lane & 7);
    int kA   = ((lane >> 4) & 1) * 8;
    int rowB = ((lane >> 4) & 1) * 8 + (lane & 7);
    int kB   = ((lane >> 3) & 1) * 8;

    int nstages = Kpad / 32;
    auto load_stage = [&](int s) {
        int buf = s & 1;
        int k0 = s * 32;
#pragma unroll
        for (int i = 0; i < 8; i++) {
            int t = tid + i * 256;
            int mat = t >> 9;
            int c = t & 511;
            int row = c >> 2, kc = c & 3;
            uint32_t dst = sb + buf * 40960 + mat * 10240 + row * 80 + kc * 16;
            const __nv_bfloat16* src =
                (mat == 0 ? gsrc0 : mat == 1 ? gsrc1 : mat == 2 ? gsrc2 : gsrc3)
                + (size_t)row * Kpad + k0 + kc * 8;
            asm volatile("cp.async.cg.shared.global [%0], [%1], 16;" :: "r"(dst), "l"(src));
        }
        asm volatile("cp.async.commit_group;");
    };

    load_stage(0);
    for (int s = 0; s < nstages; s++) {
        if (s + 1 < nstages) {
            load_stage(s + 1);
            asm volatile("cp.async.wait_group 1;");
        } else {
            asm volatile("cp.async.wait_group 0;");
        }
        __syncthreads();
        uint32_t base = sb + (s & 1) * 40960;
#pragma unroll
        for (int k16 = 0; k16 < 32; k16 += 16) {
            uint32_t ah[2][4], alr[2][4];
#pragma unroll
            for (int ma = 0; ma < 2; ma++) {
                uint32_t off = (uint32_t)(((wm + ma * 16 + rowA) * 40 + k16 + kA) * 2);
                ldm4(ah[ma], base + off);
                ldm4(alr[ma], base + 10240 + off);
            }
            uint32_t bh[4][4], blr[4][4];
#pragma unroll
            for (int nb = 0; nb < 4; nb++) {
                uint32_t off = (uint32_t)(((wn + nb * 16 + rowB) * 40 + k16 + kB) * 2);
                ldm4(bh[nb], base + 20480 + off);
                ldm4(blr[nb], base + 30720 + off);
            }
#pragma unroll
            for (int ma = 0; ma < 2; ma++)
#pragma unroll
                for (int na = 0; na < 8; na++)
                    mma_bf16(acc[ma][na], ah[ma], &bh[na >> 1][(na & 1) * 2]);
#pragma unroll
            for (int ma = 0; ma < 2; ma++)
#pragma unroll
                for (int na = 0; na < 8; na++)
                    mma_bf16(acc[ma][na], ah[ma], &blr[na >> 1][(na & 1) * 2]);
#pragma unroll
            for (int ma = 0; ma < 2; ma++)
#pragma unroll
                for (int na = 0; na < 8; na++)
                    mma_bf16(acc[ma][na], alr[ma], &bh[na >> 1][(na & 1) * 2]);
        }
        __syncthreads();
    }

    int r0 = m0 + wm + (lane >> 2);
    int cb = n0 + wn + (lane & 3) * 2;
#pragma unroll
    for (int ma = 0; ma < 2; ma++) {
        int r = r0 + ma * 16;
#pragma unroll
        for (int na = 0; na < 8; na++) {
            int col = cb + na * 8;
            if (col < Nvalid) {
                float b0v = (col < nsplit) ? bias0[col] : bias1[col - nsplit];
                float b1v = (col + 1 < nsplit) ? bias0[col + 1] : bias1[col + 1 - nsplit];
                float2 v0 = make_float2(acc[ma][na][0] + b0v, acc[ma][na][1] + b1v);
                float2 v1 = make_float2(acc[ma][na][2] + b0v, acc[ma][na][3] + b1v);
                if (ACT == 1) {
                    v0.x = fmaxf(v0.x, 0.f); v0.y = fmaxf(v0.y, 0.f);
                    v1.x = fmaxf(v1.x, 0.f); v1.y = fmaxf(v1.y, 0.f);
                }
                *(float2*)&C[(size_t)r * ldc + col] = v0;
                *(float2*)&C[(size_t)(r + 8) * ldc + col] = v1;
            }
        }
    }
}

// ---------------- weight pack for scans ----------------
__global__ void pack_w4(float4* __restrict__ dst, const float* __restrict__ src,
                        int G, int K4) {
    int i = blockIdx.x * blockDim.x + threadIdx.x;
    if (i < G * K4) {
        int k4 = i / G, g = i % G;
        const float* s = src + (size_t)g * (4 * K4) + 4 * k4;
        dst[i] = make_float4(s[0], s[1], s[2], s[3]);
    }
}

// ---------------- small fp32 SGEMM (doc MLP only) ----------------
template <int ACT>
__global__ void __launch_bounds__(256, 2)
sgemm_nt(const float* __restrict__ A, const float* __restrict__ Bm,
         const float* __restrict__ bias, float* __restrict__ C,
         int M, int N, int K) {
    __shared__ float As[2][8][128];
    __shared__ float Bs[2][8][128];
    int tid = threadIdx.x;
    int tx = tid & 15, ty = tid >> 4;
    int m0 = blockIdx.y * 128, n0 = blockIdx.x * 128;
    int lr = tid >> 1, lq = tid & 1;
    int m = m0 + lr, n = n0 + lr;
    bool nok = (n < N);
    const float* Arow = A + (size_t)m * K;
    const float* Brow = Bm + (size_t)n * K;
    float2 acc[8][4];
#pragma unroll
    for (int i = 0; i < 8; i++)
#pragma unroll
        for (int j = 0; j < 4; j++) acc[i][j] = make_float2(0.f, 0.f);
    float av[4], bv[4];
    auto load_chunk = [&](int k0) {
        int k = k0 + lq * 4;
#pragma unroll
        for (int i = 0; i < 4; i++) {
            av[i] = (k + i < K) ? Arow[k + i] : 0.f;
            bv[i] = (nok && k + i < K) ? Brow[k + i] : 0.f;
        }
    };
    auto store_chunk = [&](int buf) {
#pragma unroll
        for (int i = 0; i < 4; i++) {
            As[buf][lq * 4 + i][lr] = av[i];
            Bs[buf][lq * 4 + i][lr] = bv[i];
        }
    };
    auto compute = [&](int buf) {
#pragma unroll
        for (int kk = 0; kk < 8; kk++) {
            float4 a0 = *(const float4*)&As[buf][kk][ty * 8];
            float4 a1 = *(const float4*)&As[buf][kk][ty * 8 + 4];
            float4 b0 = *(const float4*)&Bs[buf][kk][tx * 8];
            float4 b1 = *(const float4*)&Bs[buf][kk][tx * 8 + 4];
            float a[8] = {a0.x, a0.y, a0.z, a0.w, a1.x, a1.y, a1.z, a1.w};
            float2 b2[4] = {make_float2(b0.x, b0.y), make_float2(b0.z, b0.w),
                            make_float2(b1.x, b1.y), make_float2(b1.z, b1.w)};
#pragma unroll
            for (int i = 0; i < 8; i++) {
                float2 ad = make_float2(a[i], a[i]);
#pragma unroll
                for (int j = 0; j < 4; j++) acc[i][j] = ffma2(ad, b2[j], acc[i][j]);
            }
        }
    };
    int nt = (K + 7) / 8;
    load_chunk(0);
    store_chunk(0);
    __syncthreads();
    int cur = 0;
    for (int t = 1; t < nt; t++) {
        load_chunk(t * 8);
        compute(cur);
        store_chunk(cur ^ 1);
        __syncthreads();
        cur ^= 1;
    }
    compute(cur);
#pragma unroll
    for (int i = 0; i < 8; i++) {
        int mm = m0 + ty * 8 + i;
#pragma unroll
        for (int j = 0; j < 4; j++) {
            int nn = n0 + tx * 8 + j * 2;
            if (nn + 1 < N) {
                float2 v = acc[i][j];
                if (bias) { v.x += bias[nn]; v.y += bias[nn + 1]; }
                if (ACT == 1) { v.x = fmaxf(v.x, 0.f); v.y = fmaxf(v.y, 0.f); }
                if (ACT == 2) { v.x = tanhf(v.x); v.y = tanhf(v.y); }
                *(float2*)&C[(size_t)mm * N + nn] = v;
            } else if (nn < N) {
                float v = acc[i][j].x + (bias ? bias[nn] : 0.f);
                if (ACT == 1) v = fmaxf(v, 0.f);
                if (ACT == 2) v = tanhf(v);
                C[(size_t)mm * N + nn] = v;
            }
        }
    }
}

// ---------------- bidirectional GRU recurrence (persistent, 148 blocks) --------
// grid (74, 2); GRU_ROWS batch rows per block; 608 threads.
// Writes hidden directly as bf16 hi/lo in the sent-GEMM operand layout.
__global__ void __launch_bounds__(608, 1)
gru_kernel(const float* __restrict__ gx,
           const float4* __restrict__ Wqf, const float4* __restrict__ Wqb,
           const float* __restrict__ bhhf, const float* __restrict__ bhhb,
           __nv_bfloat16* __restrict__ Hhi, __nv_bfloat16* __restrict__ Hlo) {
    extern __shared__ float sm[];
    float* hs  = sm;                      // [GRU_ROWS][200]
    float* ghs = sm + GRU_ROWS * 200;     // [GRU_ROWS][600]
    int dir = blockIdx.y;
    const float4* Wq = dir ? Wqb : Wqf;
    const float* bhh = dir ? bhhb : bhhf;
    int b0 = blockIdx.x * GRU_ROWS;
    int tid = threadIdx.x;

    for (int i = tid; i < GRU_ROWS * 200; i += blockDim.x) hs[i] = 0.f;
    __syncthreads();

    for (int t = 0; t < S_; t++) {
        int s = dir ? (S_ - 1 - t) : t;
        if (tid < 600) {
            float2 acc2[GRU_ROWS];
#pragma unroll
            for (int r = 0; r < GRU_ROWS; r++) acc2[r] = make_float2(0.f, 0.f);
            for (int k4 = 0; k4 < 50; k4++) {
                float4 w = Wq[k4 * 600 + tid];
                float2 w01 = make_float2(w.x, w.y);
                float2 w23 = make_float2(w.z, w.w);
#pragma unroll
                for (int r = 0; r < GRU_ROWS; r++) {
                    float4 h4 = *(const float4*)&hs[r * 200 + k4 * 4];
                    acc2[r] = ffma2(w01, make_float2(h4.x, h4.y), acc2[r]);
                    acc2[r] = ffma2(w23, make_float2(h4.z, h4.w), acc2[r]);
                }
            }
            float bb = bhh[tid];
#pragma unroll
            for (int r = 0; r < GRU_ROWS; r++) ghs[r * 600 + tid] = acc2[r].x + acc2[r].y + bb;
        }
        __syncthreads();
        for (int idx = tid; idx < GRU_ROWS * 200; idx += blockDim.x) {
            int r = idx / 200, j = idx % 200;
            int b = b0 + r;
            int bc = b < B_ ? b : B_ - 1;
            const float* gxr = gx + (size_t)(bc * S_ + s) * NGX + dir * 600;
            float gr = ghs[r * 600 + j];
            float gz = ghs[r * 600 + 200 + j];
            float gn = ghs[r * 600 + 400 + j];
            float rg = 1.f / (1.f + __expf(-(gxr[j] + gr)));
            float zg = 1.f / (1.f + __expf(-(gxr[200 + j] + gz)));
            float nn = tanhf(gxr[400 + j] + rg * gn);
            float hprev = hs[r * 200 + j];
            float hnew = (1.f - zg) * nn + zg * hprev;
            hs[r * 200 + j] = hnew;
            if (b < B_) {
                size_t o = (size_t)(b * S_ + s) * KP_SENT + dir * 200 + j;
                __nv_bfloat16 hb = __float2bfloat16(hnew);
                Hhi[o] = hb;
                Hlo[o] = __float2bfloat16(hnew - __bfloat162float(hb));
            }
        }
        __syncthreads();
    }
}

// ---------------- avg over sequence ----------------
__global__ void avg_kernel(const float* __restrict__ sent, const int* __restrict__ length,
                           float* __restrict__ avg) {
    int i = blockIdx.x * blockDim.x + threadIdx.x;
    if (i < B_ * H_) {
        int b = i / H_, h = i % H_;
        float s = 0.f;
        for (int t = 0; t < S_; t++) s += sent[((size_t)(b * S_ + t)) * H_ + h];
        avg[i] = s / (float)length[b];
    }
}

// ---------------- novelty scan + fused base logits (148 blocks x 7 rows) -------
__global__ void __launch_bounds__(256, 1)
nov_kernel(const float* __restrict__ sent, const float4* __restrict__ Wnq,
           const float* __restrict__ bnov,
           const float* __restrict__ wcont, const float* __restrict__ doc,
           const int* __restrict__ apos, const int* __restrict__ rpos,
           const float* __restrict__ apos_table, const float* __restrict__ rpos_table,
           const float* __restrict__ apos_w, const float* __restrict__ rpos_w,
           const float* __restrict__ apos_b, const float* __restrict__ rpos_b,
           const float* __restrict__ bcont, const float* __restrict__ bias,
           float* __restrict__ out) {
    __shared__ float sum_s[NOV_ROWS * 200];
    __shared__ float st[NOV_ROWS * 200];
    __shared__ float ps[NOV_ROWS * 200];
    __shared__ float wd[NOV_ROWS * 200];
    __shared__ float gsig[8];
    __shared__ float s_scal;
    int tid = threadIdx.x;
    int b0 = blockIdx.x * NOV_ROWS;
    if (tid == 0) s_scal = *bcont + *apos_b + *rpos_b + *bias;
    for (int i = tid; i < NOV_ROWS * 200; i += 256) {
        int r = i / 200, j = i % 200;
        int b = b0 + r; if (b >= B_) b = B_ - 1;
        sum_s[i] = 0.f;
        wd[i] = wcont[j] + doc[(size_t)b * 200 + j];
    }
    __syncthreads();
    for (int t = 0; t < S_; t++) {
        for (int i = tid; i < NOV_ROWS * 200; i += 256) {
            int r = i / 200, j = i % 200;
            int b = b0 + r; if (b >= B_) b = B_ - 1;
            st[i] = sent[((size_t)(b * S_ + t)) * 200 + j];
        }
        __syncthreads();
        if (tid < 200) {
            float2 acc2[NOV_ROWS];
#pragma unroll
            for (int r = 0; r < NOV_ROWS; r++) acc2[r] = make_float2(0.f, 0.f);
            for (int k4 = 0; k4 < 50; k4++) {
                float4 w = Wnq[k4 * 200 + tid];
                float2 w01 = make_float2(w.x, w.y);
                float2 w23 = make_float2(w.z, w.w);
#pragma unroll
                for (int r = 0; r < NOV_ROWS; r++) {
                    float4 h4 = *(const float4*)&st[r * 200 + k4 * 4];
                    acc2[r] = ffma2(w01, make_float2(h4.x, h4.y), acc2[r]);
                    acc2[r] = ffma2(w23, make_float2(h4.z, h4.w), acc2[r]);
                }
            }
            float bb = bnov[tid];
#pragma unroll
            for (int r = 0; r < NOV_ROWS; r++)
                ps[r * 200 + tid] = (acc2[r].x + acc2[r].y + bb) * tanhf(sum_s[r * 200 + tid]);
        }
        __syncthreads();
        int w = tid >> 5, lane = tid & 31;
        if (w < NOV_ROWS) {
            int b = b0 + w; if (b >= B_) b = B_ - 1;
            float acc = 0.f;
            for (int j = lane; j < 200; j += 32)
                acc += st[w * 200 + j] * wd[w * 200 + j] - ps[w * 200 + j];
            int ap = apos[b * S_ + t]; ap = ap < 0 ? 0 : (ap > 50 ? 50 : ap);
            int rp = rpos[b * S_ + t]; rp = rp < 0 ? 0 : (rp > 4 ? 4 : rp);
            for (int p = lane; p < 50; p += 32)
                acc += apos_table[ap * 50 + p] * apos_w[p] + rpos_table[rp * 50 + p] * rpos_w[p];
            for (int off = 16; off; off >>= 1) acc += __shfl_down_sync(0xffffffffu, acc, off);
            if (lane == 0) {
                float logit = acc + s_scal;
                if (b0 + w < B_) out[(size_t)(b0 + w) * S_ + t] = logit;
                gsig[w] = 1.f / (1.f + __expf(-logit));
            }
        }
        __syncthreads();
        for (int i = tid; i < NOV_ROWS * 200; i += 256) {
            int r = i / 200;
            sum_s[i] += st[i] * gsig[r];
        }
        __syncthreads();
    }
}

// ---------------- host launch ----------------
static float* sym_addr(const void* sym) {
    void* p = nullptr;
    cudaGetSymbolAddress(&p, sym);
    return (float*)p;
}

extern "C" void kernel_launch(void* const* d_in, const int* in_sizes, int n_in,
                              void* d_out, int out_size) {
    const float* seq        = (const float*)d_in[0];
    const int*   apos       = (const int*)d_in[1];
    const int*   rpos       = (const int*)d_in[2];
    const int*   length     = (const int*)d_in[3];
    const float* apos_table = (const float*)d_in[4];
    const float* rpos_table = (const float*)d_in[5];
    const float* apos_w     = (const float*)d_in[6];
    const float* apos_b     = (const float*)d_in[7];
    const float* rpos_w     = (const float*)d_in[8];
    const float* rpos_b     = (const float*)d_in[9];
    const float* Wih_f      = (const float*)d_in[10];
    const float* Whh_f      = (const float*)d_in[11];
    const float* bih_f      = (const float*)d_in[12];
    const float* bhh_f      = (const float*)d_in[13];
    const float* Wih_b      = (const float*)d_in[14];
    const float* Whh_b      = (const float*)d_in[15];
    const float* bih_b      = (const float*)d_in[16];
    const float* bhh_b      = (const float*)d_in[17];
    const float* Wsent      = (const float*)d_in[18];
    const float* bsent      = (const float*)d_in[19];
    const float* wcont      = (const float*)d_in[20];
    const float* bcont      = (const float*)d_in[21];
    const float* Wdoc1      = (const float*)d_in[22];
    const float* bdoc1      = (const float*)d_in[23];
    const float* Wdoc2      = (const float*)d_in[24];
    const float* bdoc2      = (const float*)d_in[25];
    const float* Wnov       = (const float*)d_in[26];
    const float* bnov       = (const float*)d_in[27];
    const float* bias       = (const float*)d_in[28];
    float* out = (float*)d_out;

    float* gx     = sym_addr(g_gx);
    float* sent   = sym_addr(g_sent);
    float* avg    = sym_addr(g_avg);
    float* tmp    = sym_addr(g_tmp);
    float* doc    = sym_addr(g_doc);
    float4* wqf   = (float4*)sym_addr(g_Wqf);
    float4* wqb   = (float4*)sym_addr(g_Wqb);
    float4* wnq   = (float4*)sym_addr(g_Wnq);
    __nv_bfloat16* Ahi = (__nv_bfloat16*)sym_addr(g_Ahi);
    __nv_bfloat16* Alo = (__nv_bfloat16*)sym_addr(g_Alo);
    __nv_bfloat16* Hhi = (__nv_bfloat16*)sym_addr(g_Hhi);
    __nv_bfloat16* Hlo = (__nv_bfloat16*)sym_addr(g_Hlo);
    __nv_bfloat16* Bgxhi = (__nv_bfloat16*)sym_addr(g_Bgxhi);
    __nv_bfloat16* Bgxlo = (__nv_bfloat16*)sym_addr(g_Bgxlo);
    __nv_bfloat16* Bsehi = (__nv_bfloat16*)sym_addr(g_Bsehi);
    __nv_bfloat16* Bselo = (__nv_bfloat16*)sym_addr(g_Bselo);

    cudaFuncSetAttribute(mma_gemm<0>, cudaFuncAttributeMaxDynamicSharedMemorySize, MMA_SMEM);
    cudaFuncSetAttribute(mma_gemm<1>, cudaFuncAttributeMaxDynamicSharedMemorySize, MMA_SMEM);

    // launches 1-5 (so the big gx GEMM is launch #6 for the ncu window)
    pack_w4<<<(600 * 50 + 255) / 256, 256>>>(wqf, Whh_f, 600, 50);
    pack_w4<<<(600 * 50 + 255) / 256, 256>>>(wqb, Whh_b, 600, 50);
    pack_w4<<<(200 * 50 + 255) / 256, 256>>>(wnq, Wnov, 200, 50);
    conv_hilo<<<((size_t)NP_GX * KP_GX + 255) / 256, 256>>>(
        Wih_f, Wih_b, 600, 600, E_, KP_GX, NP_GX, Bgxhi, Bgxlo);
    conv_hilo<<<((size_t)M_ * KP_GX + 255) / 256, 256>>>(
        seq, nullptr, M_, 0, E_, KP_GX, M_, Ahi, Alo);

    // launch #6: combined gx GEMM [51200,1200] = seq @ [Wih_f|Wih_b]^T + bias
    mma_gemm<0><<<dim3(NP_GX / 128, M_ / 128), 256, MMA_SMEM>>>(
        Ahi, Alo, Bgxhi, Bgxlo, bih_f, bih_b, 600, gx, NGX, NGX, KP_GX);

    // sent-weight conversion (independent; after the profiled launch)
    conv_hilo<<<((size_t)NP_SENT * KP_SENT + 255) / 256, 256>>>(
        Wsent, nullptr, 200, 0, 2 * H_, KP_SENT, NP_SENT, Bsehi, Bselo);

    // recurrence (both directions), writes Hhi/Hlo directly
    gru_kernel<<<dim3(74, 2), 608, (GRU_ROWS * 800) * 4>>>(
        gx, wqf, wqb, bhh_f, bhh_b, Hhi, Hlo);

    // sent = relu(hidden @ Wsent^T + bsent)
    mma_gemm<1><<<dim3(NP_SENT / 128, M_ / 128), 256, MMA_SMEM>>>(
        Hhi, Hlo, Bsehi, Bselo, bsent, bsent, H_, sent, H_, H_, KP_SENT);

    // avg + doc MLP (small fp32 path)
    avg_kernel<<<(B_ * H_ + 255) / 256, 256>>>(sent, length, avg);
    sgemm_nt<2><<<dim3(2, 8), 256>>>(avg, Wdoc1, bdoc1, tmp, B_, H_, H_);
    sgemm_nt<0><<<dim3(2, 8), 256>>>(tmp, Wdoc2, bdoc2, doc, B_, H_, H_);

    // novelty scan + fused base -> output
    nov_kernel<<<148, 256>>>(sent, wnq, bnov, wcont, doc, apos, rpos,
                             apos_table, rpos_table, apos_w, rpos_w,
                             apos_b, rpos_b, bcont, bias, out);
}

// round 7
// speedup vs baseline: 1.9562x; 1.1257x over previous
#include <cuda_runtime.h>
#include <cuda_fp16.h>
#include <math.h>
#include <stdint.h>

#define B_   1024
#define S_   50
#define E_   300
#define H_   200
#define M_   51200
#define NGX  1200          // stacked f|b gate width
#define KP_GX   320        // K=300 padded
#define KP_SENT 416        // K=400 padded
#define NP_GX   1280
#define NP_SENT 256
#define GRU_ROWS 14
#define NOV_ROWS 7

// ---------------- scratch (device globals; no allocations) ----------------
__device__ __align__(256) __half g_Ahi[(size_t)M_ * KP_GX];
__device__ __align__(256) __half g_Alo[(size_t)M_ * KP_GX];
__device__ __align__(256) __half g_Hhi[(size_t)M_ * KP_SENT];   // pad cols stay 0
__device__ __align__(256) __half g_Hlo[(size_t)M_ * KP_SENT];
__device__ __align__(256) __half g_Bgx[(size_t)NP_GX * KP_GX];
__device__ __align__(256) __half g_Bse[(size_t)NP_SENT * KP_SENT];
__device__ float g_gx[(size_t)M_ * NGX];
__device__ float g_sent[(size_t)M_ * H_];
__device__ float g_avg[B_ * H_];
__device__ float g_tmp[B_ * H_];
__device__ float g_doc[B_ * H_];
__device__ float g_Wqf[H_ * 3 * H_];
__device__ float g_Wqb[H_ * 3 * H_];
__device__ float g_Wnq[H_ * H_];

// ---------------- helpers ----------------
__device__ __forceinline__ uint32_t smem_u32(const void* p) {
    uint32_t a;
    asm("{ .reg .u64 t; cvta.to.shared.u64 t, %1; cvt.u32.u64 %0, t; }" : "=r"(a) : "l"(p));
    return a;
}
__device__ __forceinline__ void ldm4(uint32_t* r, uint32_t addr) {
    asm volatile("ldmatrix.sync.aligned.m8n8.x4.shared.b16 {%0,%1,%2,%3}, [%4];"
        : "=r"(r[0]), "=r"(r[1]), "=r"(r[2]), "=r"(r[3]) : "r"(addr));
}
__device__ __forceinline__ void mma_f16(float* c, const uint32_t* a, const uint32_t* b) {
    asm volatile(
        "mma.sync.aligned.m16n8k16.row.col.f32.f16.f16.f32 "
        "{%0,%1,%2,%3}, {%4,%5,%6,%7}, {%8,%9}, {%0,%1,%2,%3};"
        : "+f"(c[0]), "+f"(c[1]), "+f"(c[2]), "+f"(c[3])
        : "r"(a[0]), "r"(a[1]), "r"(a[2]), "r"(a[3]), "r"(b[0]), "r"(b[1]));
}
__device__ __forceinline__ float2 ffma2(float2 a, float2 b, float2 c) {
    unsigned long long ua = *(unsigned long long*)&a;
    unsigned long long ub = *(unsigned long long*)&b;
    unsigned long long uc = *(unsigned long long*)&c;
    unsigned long long r;
    asm("fma.rn.f32x2 %0, %1, %2, %3;" : "=l"(r) : "l"(ua), "l"(ub), "l"(uc));
    return *(float2*)&r;
}

// ---------------- fp32 -> fp16 conversions ----------------
// hi/lo split (lo != nullptr) or single fp16 (lo == nullptr); rows0|rows1 stacked.
__global__ void conv_f16(const float* __restrict__ X0, const float* __restrict__ X1,
                         int rows0, int rows1, int K, int Kpad, int totalRows,
                         __half* __restrict__ hi, __half* __restrict__ lo) {
    int i = blockIdx.x * blockDim.x + threadIdx.x;
    if (i >= totalRows * Kpad) return;
    int row = i / Kpad, k = i - row * Kpad;
    float x = 0.f;
    if (k < K) {
        if (row < rows0) x = X0[(size_t)row * K + k];
        else if (X1 && row < rows0 + rows1) x = X1[(size_t)(row - rows0) * K + k];
    }
    __half h = __float2half_rn(x);
    hi[i] = h;
    if (lo) lo[i] = __float2half_rn(x - __half2float(h));
}

// ---------------- 2-pass split-fp16 tensor-core GEMM (mma.sync) ----------------
// C[m,n] = act( (Ahi+Alo)[m,:] . B[n,:] + bias[n] );  A hi/lo fp16, B single fp16.
// 256 threads = 8 warps (4m x 2n), CTA tile 128x128, BK=32, cp.async double buffer.
// smem: 3 matrices per stage (Ahi, Alo, B), 128 rows x pitch-40 halves.
#define MMA_SMEM (2 * 3 * 10240)

template <int ACT>
__global__ void __launch_bounds__(256)
mma_gemm(const __half* __restrict__ Ahi, const __half* __restrict__ Alo,
         const __half* __restrict__ Bm,
         const float* __restrict__ bias0, const float* __restrict__ bias1, int nsplit,
         float* __restrict__ C, int ldc, int Nvalid, int Kpad) {
    extern __shared__ __align__(16) __half smbuf[];
    uint32_t sb = smem_u32(smbuf);
    int tid = threadIdx.x;
    int w = tid >> 5, lane = tid & 31;
    int wm = (w >> 1) * 32, wn = (w & 1) * 64;
    int m0 = blockIdx.y * 128, n0 = blockIdx.x * 128;

    const __half* gsrc0 = Ahi + (size_t)m0 * Kpad;
    const __half* gsrc1 = Alo + (size_t)m0 * Kpad;
    const __half* gsrc2 = Bm + (size_t)n0 * Kpad;

    float acc[2][8][4];
#pragma unroll
    for (int i = 0; i < 2; i++)
#pragma unroll
        for (int j = 0; j < 8; j++)
#pragma unroll
            for (int e = 0; e < 4; e++) acc[i][j][e] = 0.f;

    int rowA = ((lane >> 3) & 1) * 8 + (lane & 7);
    int kA   = ((lane >> 4) & 1) * 8;
    int rowB = ((lane >> 4) & 1) * 8 + (lane & 7);
    int kB   = ((lane >> 3) & 1) * 8;

    int nstages = Kpad / 32;
    auto load_stage = [&](int s) {
        int buf = s & 1;
        int k0 = s * 32;
#pragma unroll
        for (int i = 0; i < 6; i++) {
            int t = tid + i * 256;        // 0..1535
            int mat = t >> 9;             // 0..2
            int c = t & 511;
            int row = c >> 2, kc = c & 3;
            uint32_t dst = sb + buf * 30720 + mat * 10240 + row * 80 + kc * 16;
            const __half* src =
                (mat == 0 ? gsrc0 : mat == 1 ? gsrc1 : gsrc2)
                + (size_t)row * Kpad + k0 + kc * 8;
            asm volatile("cp.async.cg.shared.global [%0], [%1], 16;" :: "r"(dst), "l"(src));
        }
        asm volatile("cp.async.commit_group;");
    };

    load_stage(0);
    for (int s = 0; s < nstages; s++) {
        if (s + 1 < nstages) {
            load_stage(s + 1);
            asm volatile("cp.async.wait_group 1;");
        } else {
            asm volatile("cp.async.wait_group 0;");
        }
        __syncthreads();
        uint32_t base = sb + (s & 1) * 30720;
#pragma unroll
        for (int k16 = 0; k16 < 32; k16 += 16) {
            uint32_t ah[2][4], al[2][4];
#pragma unroll
            for (int ma = 0; ma < 2; ma++) {
                uint32_t off = (uint32_t)(((wm + ma * 16 + rowA) * 40 + k16 + kA) * 2);
                ldm4(ah[ma], base + off);
                ldm4(al[ma], base + 10240 + off);
            }
            uint32_t bh[4][4];
#pragma unroll
            for (int nb = 0; nb < 4; nb++) {
                uint32_t off = (uint32_t)(((wn + nb * 16 + rowB) * 40 + k16 + kB) * 2);
                ldm4(bh[nb], base + 20480 + off);
            }
#pragma unroll
            for (int ma = 0; ma < 2; ma++)
#pragma unroll
                for (int na = 0; na < 8; na++)
                    mma_f16(acc[ma][na], ah[ma], &bh[na >> 1][(na & 1) * 2]);
#pragma unroll
            for (int ma = 0; ma < 2; ma++)
#pragma unroll
                for (int na = 0; na < 8; na++)
                    mma_f16(acc[ma][na], al[ma], &bh[na >> 1][(na & 1) * 2]);
        }
        __syncthreads();
    }

    int r0 = m0 + wm + (lane >> 2);
    int cb = n0 + wn + (lane & 3) * 2;
#pragma unroll
    for (int ma = 0; ma < 2; ma++) {
        int r = r0 + ma * 16;
#pragma unroll
        for (int na = 0; na < 8; na++) {
            int col = cb + na * 8;
            if (col < Nvalid) {
                float b0v = (col < nsplit) ? bias0[col] : bias1[col - nsplit];
                float b1v = (col + 1 < nsplit) ? bias0[col + 1] : bias1[col + 1 - nsplit];
                float2 v0 = make_float2(acc[ma][na][0] + b0v, acc[ma][na][1] + b1v);
                float2 v1 = make_float2(acc[ma][na][2] + b0v, acc[ma][na][3] + b1v);
                if (ACT == 1) {
                    v0.x = fmaxf(v0.x, 0.f); v0.y = fmaxf(v0.y, 0.f);
                    v1.x = fmaxf(v1.x, 0.f); v1.y = fmaxf(v1.y, 0.f);
                }
                *(float2*)&C[(size_t)r * ldc + col] = v0;
                *(float2*)&C[(size_t)(r + 8) * ldc + col] = v1;
            }
        }
    }
}

// ---------------- weight pack for scans ----------------
__global__ void pack_w4(float4* __restrict__ dst, const float* __restrict__ src,
                        int G, int K4) {
    int i = blockIdx.x * blockDim.x + threadIdx.x;
    if (i < G * K4) {
        int k4 = i / G, g = i % G;
        const float* s = src + (size_t)g * (4 * K4) + 4 * k4;
        dst[i] = make_float4(s[0], s[1], s[2], s[3]);
    }
}

// ---------------- small fp32 SGEMM (doc MLP only) ----------------
template <int ACT>
__global__ void __launch_bounds__(256, 2)
sgemm_nt(const float* __restrict__ A, const float* __restrict__ Bm,
         const float* __restrict__ bias, float* __restrict__ C,
         int M, int N, int K) {
    __shared__ float As[2][8][128];
    __shared__ float Bs[2][8][128];
    int tid = threadIdx.x;
    int tx = tid & 15, ty = tid >> 4;
    int m0 = blockIdx.y * 128, n0 = blockIdx.x * 128;
    int lr = tid >> 1, lq = tid & 1;
    int m = m0 + lr, n = n0 + lr;
    bool nok = (n < N);
    const float* Arow = A + (size_t)m * K;
    const float* Brow = Bm + (size_t)n * K;
    float2 acc[8][4];
#pragma unroll
    for (int i = 0; i < 8; i++)
#pragma unroll
        for (int j = 0; j < 4; j++) acc[i][j] = make_float2(0.f, 0.f);
    float av[4], bv[4];
    auto load_chunk = [&](int k0) {
        int k = k0 + lq * 4;
#pragma unroll
        for (int i = 0; i < 4; i++) {
            av[i] = (k + i < K) ? Arow[k + i] : 0.f;
            bv[i] = (nok && k + i < K) ? Brow[k + i] : 0.f;
        }
    };
    auto store_chunk = [&](int buf) {
#pragma unroll
        for (int i = 0; i < 4; i++) {
            As[buf][lq * 4 + i][lr] = av[i];
            Bs[buf][lq * 4 + i][lr] = bv[i];
        }
    };
    auto compute = [&](int buf) {
#pragma unroll
        for (int kk = 0; kk < 8; kk++) {
            float4 a0 = *(const float4*)&As[buf][kk][ty * 8];
            float4 a1 = *(const float4*)&As[buf][kk][ty * 8 + 4];
            float4 b0 = *(const float4*)&Bs[buf][kk][tx * 8];
            float4 b1 = *(const float4*)&Bs[buf][kk][tx * 8 + 4];
            float a[8] = {a0.x, a0.y, a0.z, a0.w, a1.x, a1.y, a1.z, a1.w};
            float2 b2[4] = {make_float2(b0.x, b0.y), make_float2(b0.z, b0.w),
                            make_float2(b1.x, b1.y), make_float2(b1.z, b1.w)};
#pragma unroll
            for (int i = 0; i < 8; i++) {
                float2 ad = make_float2(a[i], a[i]);
#pragma unroll
                for (int j = 0; j < 4; j++) acc[i][j] = ffma2(ad, b2[j], acc[i][j]);
            }
        }
    };
    int nt = (K + 7) / 8;
    load_chunk(0);
    store_chunk(0);
    __syncthreads();
    int cur = 0;
    for (int t = 1; t < nt; t++) {
        load_chunk(t * 8);
        compute(cur);
        store_chunk(cur ^ 1);
        __syncthreads();
        cur ^= 1;
    }
    compute(cur);
#pragma unroll
    for (int i = 0; i < 8; i++) {
        int mm = m0 + ty * 8 + i;
#pragma unroll
        for (int j = 0; j < 4; j++) {
            int nn = n0 + tx * 8 + j * 2;
            if (nn + 1 < N) {
                float2 v = acc[i][j];
                if (bias) { v.x += bias[nn]; v.y += bias[nn + 1]; }
                if (ACT == 1) { v.x = fmaxf(v.x, 0.f); v.y = fmaxf(v.y, 0.f); }
                if (ACT == 2) { v.x = tanhf(v.x); v.y = tanhf(v.y); }
                *(float2*)&C[(size_t)mm * N + nn] = v;
            } else if (nn < N) {
                float v = acc[i][j].x + (bias ? bias[nn] : 0.f);
                if (ACT == 1) v = fmaxf(v, 0.f);
                if (ACT == 2) v = tanhf(v);
                C[(size_t)mm * N + nn] = v;
            }
        }
    }
}

// ---------------- bidirectional GRU recurrence (persistent, 148 blocks) --------
__global__ void __launch_bounds__(608, 1)
gru_kernel(const float* __restrict__ gx,
           const float4* __restrict__ Wqf, const float4* __restrict__ Wqb,
           const float* __restrict__ bhhf, const float* __restrict__ bhhb,
           __half* __restrict__ Hhi, __half* __restrict__ Hlo) {
    extern __shared__ float sm[];
    float* hs  = sm;                      // [GRU_ROWS][200]
    float* ghs = sm + GRU_ROWS * 200;     // [GRU_ROWS][600]
    int dir = blockIdx.y;
    const float4* Wq = dir ? Wqb : Wqf;
    const float* bhh = dir ? bhhb : bhhf;
    int b0 = blockIdx.x * GRU_ROWS;
    int tid = threadIdx.x;

    for (int i = tid; i < GRU_ROWS * 200; i += blockDim.x) hs[i] = 0.f;
    __syncthreads();

    for (int t = 0; t < S_; t++) {
        int s = dir ? (S_ - 1 - t) : t;
        if (tid < 600) {
            float2 acc2[GRU_ROWS];
#pragma unroll
            for (int r = 0; r < GRU_ROWS; r++) acc2[r] = make_float2(0.f, 0.f);
            for (int k4 = 0; k4 < 50; k4++) {
                float4 w = Wq[k4 * 600 + tid];
                float2 w01 = make_float2(w.x, w.y);
                float2 w23 = make_float2(w.z, w.w);
#pragma unroll
                for (int r = 0; r < GRU_ROWS; r++) {
                    float4 h4 = *(const float4*)&hs[r * 200 + k4 * 4];
                    acc2[r] = ffma2(w01, make_float2(h4.x, h4.y), acc2[r]);
                    acc2[r] = ffma2(w23, make_float2(h4.z, h4.w), acc2[r]);
                }
            }
            float bb = bhh[tid];
#pragma unroll
            for (int r = 0; r < GRU_ROWS; r++) ghs[r * 600 + tid] = acc2[r].x + acc2[r].y + bb;
        }
        __syncthreads();
        for (int idx = tid; idx < GRU_ROWS * 200; idx += blockDim.x) {
            int r = idx / 200, j = idx % 200;
            int b = b0 + r;
            int bc = b < B_ ? b : B_ - 1;
            const float* gxr = gx + (size_t)(bc * S_ + s) * NGX + dir * 600;
            float gr = ghs[r * 600 + j];
            float gz = ghs[r * 600 + 200 + j];
            float gn = ghs[r * 600 + 400 + j];
            float rg = 1.f / (1.f + __expf(-(gxr[j] + gr)));
            float zg = 1.f / (1.f + __expf(-(gxr[200 + j] + gz)));
            float nn = tanhf(gxr[400 + j] + rg * gn);
            float hprev = hs[r * 200 + j];
            float hnew = (1.f - zg) * nn + zg * hprev;
            hs[r * 200 + j] = hnew;
            if (b < B_) {
                size_t o = (size_t)(b * S_ + s) * KP_SENT + dir * 200 + j;
                __half hb = __float2half_rn(hnew);
                Hhi[o] = hb;
                Hlo[o] = __float2half_rn(hnew - __half2float(hb));
            }
        }
        __syncthreads();
    }
}

// ---------------- avg over sequence ----------------
__global__ void avg_kernel(const float* __restrict__ sent, const int* __restrict__ length,
                           float* __restrict__ avg) {
    int i = blockIdx.x * blockDim.x + threadIdx.x;
    if (i < B_ * H_) {
        int b = i / H_, h = i % H_;
        float s = 0.f;
        for (int t = 0; t < S_; t++) s += sent[((size_t)(b * S_ + t)) * H_ + h];
        avg[i] = s / (float)length[b];
    }
}

// ---------------- novelty scan + fused base logits (148 blocks x 7 rows) -------
__global__ void __launch_bounds__(256, 1)
nov_kernel(const float* __restrict__ sent, const float4* __restrict__ Wnq,
           const float* __restrict__ bnov,
           const float* __restrict__ wcont, const float* __restrict__ doc,
           const int* __restrict__ apos, const int* __restrict__ rpos,
           const float* __restrict__ apos_table, const float* __restrict__ rpos_table,
           const float* __restrict__ apos_w, const float* __restrict__ rpos_w,
           const float* __restrict__ apos_b, const float* __restrict__ rpos_b,
           const float* __restrict__ bcont, const float* __restrict__ bias,
           float* __restrict__ out) {
    __shared__ float sum_s[NOV_ROWS * 200];
    __shared__ float st[NOV_ROWS * 200];
    __shared__ float ps[NOV_ROWS * 200];
    __shared__ float wd[NOV_ROWS * 200];
    __shared__ float gsig[8];
    __shared__ float s_scal;
    int tid = threadIdx.x;
    int b0 = blockIdx.x * NOV_ROWS;
    if (tid == 0) s_scal = *bcont + *apos_b + *rpos_b + *bias;
    for (int i = tid; i < NOV_ROWS * 200; i += 256) {
        int r = i / 200, j = i % 200;
        int b = b0 + r; if (b >= B_) b = B_ - 1;
        sum_s[i] = 0.f;
        wd[i] = wcont[j] + doc[(size_t)b * 200 + j];
    }
    __syncthreads();
    for (int t = 0; t < S_; t++) {
        for (int i = tid; i < NOV_ROWS * 200; i += 256) {
            int r = i / 200, j = i % 200;
            int b = b0 + r; if (b >= B_) b = B_ - 1;
            st[i] = sent[((size_t)(b * S_ + t)) * 200 + j];
        }
        __syncthreads();
        if (tid < 200) {
            float2 acc2[NOV_ROWS];
#pragma unroll
            for (int r = 0; r < NOV_ROWS; r++) acc2[r] = make_float2(0.f, 0.f);
            for (int k4 = 0; k4 < 50; k4++) {
                float4 w = Wnq[k4 * 200 + tid];
                float2 w01 = make_float2(w.x, w.y);
                float2 w23 = make_float2(w.z, w.w);
#pragma unroll
                for (int r = 0; r < NOV_ROWS; r++) {
                    float4 h4 = *(const float4*)&st[r * 200 + k4 * 4];
                    acc2[r] = ffma2(w01, make_float2(h4.x, h4.y), acc2[r]);
                    acc2[r] = ffma2(w23, make_float2(h4.z, h4.w), acc2[r]);
                }
            }
            float bb = bnov[tid];
#pragma unroll
            for (int r = 0; r < NOV_ROWS; r++)
                ps[r * 200 + tid] = (acc2[r].x + acc2[r].y + bb) * tanhf(sum_s[r * 200 + tid]);
        }
        __syncthreads();
        int w = tid >> 5, lane = tid & 31;
        if (w < NOV_ROWS) {
            int b = b0 + w; if (b >= B_) b = B_ - 1;
            float acc = 0.f;
            for (int j = lane; j < 200; j += 32)
                acc += st[w * 200 + j] * wd[w * 200 + j] - ps[w * 200 + j];
            int ap = apos[b * S_ + t]; ap = ap < 0 ? 0 : (ap > 50 ? 50 : ap);
            int rp = rpos[b * S_ + t]; rp = rp < 0 ? 0 : (rp > 4 ? 4 : rp);
            for (int p = lane; p < 50; p += 32)
                acc += apos_table[ap * 50 + p] * apos_w[p] + rpos_table[rp * 50 + p] * rpos_w[p];
            for (int off = 16; off; off >>= 1) acc += __shfl_down_sync(0xffffffffu, acc, off);
            if (lane == 0) {
                float logit = acc + s_scal;
                if (b0 + w < B_) out[(size_t)(b0 + w) * S_ + t] = logit;
                gsig[w] = 1.f / (1.f + __expf(-logit));
            }
        }
        __syncthreads();
        for (int i = tid; i < NOV_ROWS * 200; i += 256) {
            int r = i / 200;
            sum_s[i] += st[i] * gsig[r];
        }
        __syncthreads();
    }
}

// ---------------- host launch ----------------
static float* sym_addr(const void* sym) {
    void* p = nullptr;
    cudaGetSymbolAddress(&p, sym);
    return (float*)p;
}

extern "C" void kernel_launch(void* const* d_in, const int* in_sizes, int n_in,
                              void* d_out, int out_size) {
    const float* seq        = (const float*)d_in[0];
    const int*   apos       = (const int*)d_in[1];
    const int*   rpos       = (const int*)d_in[2];
    const int*   length     = (const int*)d_in[3];
    const float* apos_table = (const float*)d_in[4];
    const float* rpos_table = (const float*)d_in[5];
    const float* apos_w     = (const float*)d_in[6];
    const float* apos_b     = (const float*)d_in[7];
    const float* rpos_w     = (const float*)d_in[8];
    const float* rpos_b     = (const float*)d_in[9];
    const float* Wih_f      = (const float*)d_in[10];
    const float* Whh_f      = (const float*)d_in[11];
    const float* bih_f      = (const float*)d_in[12];
    const float* bhh_f      = (const float*)d_in[13];
    const float* Wih_b      = (const float*)d_in[14];
    const float* Whh_b      = (const float*)d_in[15];
    const float* bih_b      = (const float*)d_in[16];
    const float* bhh_b      = (const float*)d_in[17];
    const float* Wsent      = (const float*)d_in[18];
    const float* bsent      = (const float*)d_in[19];
    const float* wcont      = (const float*)d_in[20];
    const float* bcont      = (const float*)d_in[21];
    const float* Wdoc1      = (const float*)d_in[22];
    const float* bdoc1      = (const float*)d_in[23];
    const float* Wdoc2      = (const float*)d_in[24];
    const float* bdoc2      = (const float*)d_in[25];
    const float* Wnov       = (const float*)d_in[26];
    const float* bnov       = (const float*)d_in[27];
    const float* bias       = (const float*)d_in[28];
    float* out = (float*)d_out;

    float* gx     = sym_addr(g_gx);
    float* sent   = sym_addr(g_sent);
    float* avg    = sym_addr(g_avg);
    float* tmp    = sym_addr(g_tmp);
    float* doc    = sym_addr(g_doc);
    float4* wqf   = (float4*)sym_addr(g_Wqf);
    float4* wqb   = (float4*)sym_addr(g_Wqb);
    float4* wnq   = (float4*)sym_addr(g_Wnq);
    __half* Ahi = (__half*)sym_addr(g_Ahi);
    __half* Alo = (__half*)sym_addr(g_Alo);
    __half* Hhi = (__half*)sym_addr(g_Hhi);
    __half* Hlo = (__half*)sym_addr(g_Hlo);
    __half* Bgx = (__half*)sym_addr(g_Bgx);
    __half* Bse = (__half*)sym_addr(g_Bse);

    cudaFuncSetAttribute(mma_gemm<0>, cudaFuncAttributeMaxDynamicSharedMemorySize, MMA_SMEM);
    cudaFuncSetAttribute(mma_gemm<1>, cudaFuncAttributeMaxDynamicSharedMemorySize, MMA_SMEM);

    // small preps
    pack_w4<<<(600 * 50 + 255) / 256, 256>>>(wqf, Whh_f, 600, 50);
    pack_w4<<<(600 * 50 + 255) / 256, 256>>>(wqb, Whh_b, 600, 50);
    pack_w4<<<(200 * 50 + 255) / 256, 256>>>(wnq, Wnov, 200, 50);
    conv_f16<<<((size_t)NP_GX * KP_GX + 255) / 256, 256>>>(
        Wih_f, Wih_b, 600, 600, E_, KP_GX, NP_GX, Bgx, nullptr);
    conv_f16<<<((size_t)M_ * KP_GX + 255) / 256, 256>>>(
        seq, nullptr, M_, 0, E_, KP_GX, M_, Ahi, Alo);

    // combined gx GEMM [51200,1200] = seq @ [Wih_f|Wih_b]^T + bias
    mma_gemm<0><<<dim3(NP_GX / 128, M_ / 128), 256, MMA_SMEM>>>(
        Ahi, Alo, Bgx, bih_f, bih_b, 600, gx, NGX, NGX, KP_GX);

    // sent-weight conversion (independent)
    conv_f16<<<((size_t)NP_SENT * KP_SENT + 255) / 256, 256>>>(
        Wsent, nullptr, 200, 0, 2 * H_, KP_SENT, NP_SENT, Bse, nullptr);

    // recurrence (both directions), writes Hhi/Hlo directly
    gru_kernel<<<dim3(74, 2), 608, (GRU_ROWS * 800) * 4>>>(
        gx, wqf, wqb, bhh_f, bhh_b, Hhi, Hlo);

    // sent = relu(hidden @ Wsent^T + bsent)
    mma_gemm<1><<<dim3(NP_SENT / 128, M_ / 128), 256, MMA_SMEM>>>(
        Hhi, Hlo, Bse, bsent, bsent, H_, sent, H_, H_, KP_SENT);

    // avg + doc MLP (small fp32 path)
    avg_kernel<<<(B_ * H_ + 255) / 256, 256>>>(sent, length, avg);
    sgemm_nt<2><<<dim3(2, 8), 256>>>(avg, Wdoc1, bdoc1, tmp, B_, H_, H_);
    sgemm_nt<0><<<dim3(2, 8), 256>>>(tmp, Wdoc2, bdoc2, doc, B_, H_, H_);

    // novelty scan + fused base -> output
    nov_kernel<<<148, 256>>>(sent, wnq, bnov, wcont, doc, apos, rpos,
                             apos_table, rpos_table, apos_w, rpos_w,
                             apos_b, rpos_b, bcont, bias, out);
}